// round 12
// baseline (speedup 1.0000x reference)
#include <cuda_runtime.h>
#include <cuda_fp16.h>
#include <math.h>
#include <stdint.h>

// Problem constants
#define Bz 64
#define Tz 512
#define Cz 512
#define Hz 512
#define Gz 2048    // 4*H
#define Mz (Bz*Tz) // 32768
#define NSLICE 32  // h-col slices (CTAs per group)
#define NGRP 4     // batch groups (16 rows each)
#define K2P 520    // W_hh2 image row stride (halves) -> 1040 B, conflict-free
#define HROWB 1040 // h tile row stride (bytes), conflict-free

// ---------------- device scratch (static, no allocation) ----------------
__device__ float g_xp[(size_t)Mz * Gz];      // [m][g]
__device__ float g_hseq[(size_t)Mz * Hz];    // [m][c]
__device__ __half g_xh[(size_t)Mz * Cz];     // fp16 x [m][c]
__device__ __half g_w16a[Gz * Cz];           // W_ih1 fp16 [g][k]
__device__ float g_bias1[Gz];
__device__ float g_bias2[Gz];
__device__ uint32_t g_wr1[NSLICE * 8 * 32 * 64];      // W_hh1 B-fragments
__device__ uint32_t g_wr2[NSLICE * 8 * 32 * 64];      // W_ih2 B-fragments
__device__ __half g_w2img[(size_t)NSLICE * 64 * K2P]; // per-slice W_hh2 images
__device__ __half g_h1[NGRP][2][16 * Hz];    // h1 fp16 double buffer
__device__ __half g_h2[NGRP][2][16 * Hz];    // h2 fp16 double buffer
__device__ unsigned long long g_flag1[NGRP][NSLICE][16];  // h1-ready flags (128B)
__device__ unsigned long long g_flag2[NGRP][NSLICE][16];  // h2-ready flags (128B)

// ==================== helpers ====================
__device__ __forceinline__ uint32_t smem_u32(const void* p) {
    uint32_t a;
    asm("{ .reg .u64 t; cvta.to.shared.u64 t, %1; cvt.u32.u64 %0, t; }" : "=r"(a) : "l"(p));
    return a;
}
__device__ __forceinline__ void cpa16(uint32_t dst_smem, const void* src) {
    asm volatile("cp.async.cg.shared.global [%0], [%1], 16;" :: "r"(dst_smem), "l"(src));
}
__device__ __forceinline__ void cpa_commit() { asm volatile("cp.async.commit_group;"); }
__device__ __forceinline__ void cpa_wait0()  { asm volatile("cp.async.wait_group 0;" ::: "memory"); }
__device__ __forceinline__ void cpa_wait1()  { asm volatile("cp.async.wait_group 1;" ::: "memory"); }

__device__ __forceinline__ void flag_release(unsigned long long* p, unsigned long long v) {
    asm volatile("st.release.gpu.global.u64 [%0], %1;" :: "l"(p), "l"(v) : "memory");
}
__device__ __forceinline__ unsigned long long flag_acquire(const unsigned long long* p) {
    unsigned long long v;
    asm volatile("ld.acquire.gpu.global.u64 %0, [%1];" : "=l"(v) : "l"(p) : "memory");
    return v;
}

__device__ __forceinline__ void mma16816(float* c,
    uint32_t a0, uint32_t a1, uint32_t a2, uint32_t a3, uint32_t b0, uint32_t b1)
{
    asm volatile(
        "mma.sync.aligned.m16n8k16.row.col.f32.f16.f16.f32 "
        "{%0,%1,%2,%3}, {%4,%5,%6,%7}, {%8,%9}, {%0,%1,%2,%3};"
        : "+f"(c[0]), "+f"(c[1]), "+f"(c[2]), "+f"(c[3])
        : "r"(a0), "r"(a1), "r"(a2), "r"(a3), "r"(b0), "r"(b1));
}

__device__ __forceinline__ void ldsm4(uint32_t& a0, uint32_t& a1, uint32_t& a2, uint32_t& a3,
                                      uint32_t addr)
{
    asm volatile("ldmatrix.sync.aligned.m8n8.x4.shared.b16 {%0,%1,%2,%3}, [%4];"
                 : "=r"(a0), "=r"(a1), "=r"(a2), "=r"(a3) : "r"(addr));
}

__device__ __forceinline__ float sig_(float x)  { return __fdividef(1.f, 1.f + __expf(-x)); }
__device__ __forceinline__ float tanh_(float x) { return 1.f - 2.f * __fdividef(1.f, __expf(2.f * x) + 1.f); }

// ---------------- prep: fp16 W_ih1, fold biases ----------------
__global__ void lstm_prep(const float* __restrict__ Wih1,
                          const float* __restrict__ bih1,
                          const float* __restrict__ bhh1,
                          const float* __restrict__ bih2,
                          const float* __restrict__ bhh2)
{
    int i = blockIdx.x * blockDim.x + threadIdx.x;
    if (i < Gz * Cz) g_w16a[i] = __float2half(Wih1[i]);
    if (i < Gz) {
        g_bias1[i] = bih1[i] + bhh1[i];
        g_bias2[i] = bih2[i] + bhh2[i];
    }
}

// ---------------- prep: W_hh1 / W_ih2 -> mma.sync B fragments ----------------
__global__ void prep_wr(const float* __restrict__ Whh1, const float* __restrict__ Wih2)
{
    int e = blockIdx.x * blockDim.x + threadIdx.x;
    if (e >= 2 * NSLICE * 8 * 32 * 32) return;
    int ks   = e & 31;
    int lane = (e >> 5) & 31;
    int w    = (e >> 10) & 7;
    int n    = (e >> 13) & 31;
    int l    = e >> 18;
    const float* W = l ? Wih2 : Whh1;
    int wrow = (w >> 1) * Hz + n * 16 + (w & 1) * 8 + (lane >> 2);
    int kb   = ks * 16 + (lane & 3) * 2;
    const float* r = W + (size_t)wrow * Hz;
    __half2 v0 = __floats2half2_rn(r[kb],     r[kb + 1]);
    __half2 v1 = __floats2half2_rn(r[kb + 8], r[kb + 9]);
    uint32_t* dst = l ? g_wr2 : g_wr1;
    size_t idx = ((((size_t)n * 8 + w) * 32 + lane) * 32 + ks) * 2;
    dst[idx]     = *(const uint32_t*)&v0;
    dst[idx + 1] = *(const uint32_t*)&v1;
}

// ---------------- prep: W_hh2 per-slice fp16 image (stride K2P) -----------
__global__ void prep_w2img(const float* __restrict__ Whh2)
{
    int e = blockIdx.x * blockDim.x + threadIdx.x;   // [n][q][k]
    if (e >= NSLICE * 64 * 512) return;
    int k = e & 511;
    int q = (e >> 9) & 63;
    int n = e >> 15;
    int row = (q >> 4) * Hz + n * 16 + (q & 15);
    g_w2img[((size_t)n * 64 + q) * K2P + k] = __float2half(Whh2[(size_t)row * Hz + k]);
}

// ---------------- convert x (B,C,T) -> fp16 [b*T+t][c] ----------------
__global__ void __launch_bounds__(256)
convert_x(const float* __restrict__ x, __half* __restrict__ xh)
{
    __shared__ float smt[32][33];
    const int t0 = blockIdx.x * 32;
    const int c0 = blockIdx.y * 32;
    const int b  = blockIdx.z;
    const int tx = threadIdx.x;
    const int ty = threadIdx.y;
#pragma unroll
    for (int i = 0; i < 4; i++)
        smt[ty + i * 8][tx] = x[(size_t)b * (Cz * Tz) + (size_t)(c0 + ty + i * 8) * Tz + t0 + tx];
    __syncthreads();
#pragma unroll
    for (int i = 0; i < 4; i++)
        xh[((size_t)b * Tz + t0 + ty + i * 8) * Cz + c0 + tx] = __float2half(smt[tx][ty + i * 8]);
}

// ---------------- fp16 tensor-core xp GEMM (layer 1 only) ----------------
#define BKP 40
#define ASZ (128 * BKP * 2)
__global__ void __launch_bounds__(256)
gemm_xp16(const __half* __restrict__ A,
          const __half* __restrict__ Bw,
          const float* __restrict__ bias,
          float* __restrict__ Cout)
{
    __shared__ __half sbuf[2 * 2 * 128 * BKP];
    const uint32_t s0 = smem_u32(sbuf);

    const int m0 = blockIdx.y * 128;
    const int g0 = blockIdx.x * 128;
    const int tid = threadIdx.x;
    const int w = tid >> 5;
    const int lane = tid & 31;
    const int wm = (w >> 1) * 32;
    const int wn = (w & 1) * 64;

    float c_[2][8][4];
#pragma unroll
    for (int mt = 0; mt < 2; mt++)
#pragma unroll
        for (int q = 0; q < 8; q++)
#pragma unroll
            for (int i = 0; i < 4; i++) c_[mt][q][i] = 0.f;

    const int zr0 = tid >> 2, zs0 = tid & 3;
    const int zr1 = (tid + 256) >> 2, zs1 = tid & 3;

    const uint32_t a_off = (uint32_t)(((wm + (lane & 15)) * BKP + (lane >> 4) * 8) * 2);
    const uint32_t b_off = (uint32_t)(((wn + ((lane >> 4) & 1) * 8 + (lane & 7)) * BKP
                                      + ((lane >> 3) & 1) * 8) * 2);

    {
        cpa16(s0 + (zr0 * BKP + zs0 * 8) * 2, A + (size_t)(m0 + zr0) * Cz + zs0 * 8);
        cpa16(s0 + (zr1 * BKP + zs1 * 8) * 2, A + (size_t)(m0 + zr1) * Cz + zs1 * 8);
        cpa16(s0 + 2 * ASZ + (zr0 * BKP + zs0 * 8) * 2, Bw + (size_t)(g0 + zr0) * Cz + zs0 * 8);
        cpa16(s0 + 2 * ASZ + (zr1 * BKP + zs1 * 8) * 2, Bw + (size_t)(g0 + zr1) * Cz + zs1 * 8);
        cpa_commit();
    }

    for (int c = 0; c < 16; c++) {
        const int buf = c & 1;
        if (c < 15) {
            const int nb = buf ^ 1;
            const int k0 = (c + 1) * 32;
            cpa16(s0 + nb * ASZ + (zr0 * BKP + zs0 * 8) * 2,
                  A + (size_t)(m0 + zr0) * Cz + k0 + zs0 * 8);
            cpa16(s0 + nb * ASZ + (zr1 * BKP + zs1 * 8) * 2,
                  A + (size_t)(m0 + zr1) * Cz + k0 + zs1 * 8);
            cpa16(s0 + (2 + nb) * ASZ + (zr0 * BKP + zs0 * 8) * 2,
                  Bw + (size_t)(g0 + zr0) * Cz + k0 + zs0 * 8);
            cpa16(s0 + (2 + nb) * ASZ + (zr1 * BKP + zs1 * 8) * 2,
                  Bw + (size_t)(g0 + zr1) * Cz + k0 + zs1 * 8);
            cpa_commit();
            cpa_wait1();
        } else {
            cpa_wait0();
        }
        __syncthreads();

        const uint32_t ab = s0 + buf * ASZ + a_off;
        const uint32_t bb = s0 + (2 + buf) * ASZ + b_off;
#pragma unroll
        for (int ks = 0; ks < 2; ks++) {
            uint32_t a[2][4];
#pragma unroll
            for (int mt = 0; mt < 2; mt++)
                ldsm4(a[mt][0], a[mt][1], a[mt][2], a[mt][3],
                      ab + (uint32_t)(mt * 16 * BKP * 2 + ks * 32));
#pragma unroll
            for (int j = 0; j < 4; j++) {
                uint32_t r0, r1, r2, r3;
                ldsm4(r0, r1, r2, r3, bb + (uint32_t)(j * 16 * BKP * 2 + ks * 32));
                mma16816(c_[0][2 * j],     a[0][0], a[0][1], a[0][2], a[0][3], r0, r1);
                mma16816(c_[1][2 * j],     a[1][0], a[1][1], a[1][2], a[1][3], r0, r1);
                mma16816(c_[0][2 * j + 1], a[0][0], a[0][1], a[0][2], a[0][3], r2, r3);
                mma16816(c_[1][2 * j + 1], a[1][0], a[1][1], a[1][2], a[1][3], r2, r3);
            }
        }
        __syncthreads();
    }

#pragma unroll
    for (int q = 0; q < 8; q++) {
        const int gc = g0 + wn + q * 8 + (lane & 3) * 2;
        const float bv0 = bias[gc];
        const float bv1 = bias[gc + 1];
#pragma unroll
        for (int mt = 0; mt < 2; mt++) {
            const int r0 = m0 + wm + mt * 16 + (lane >> 2);
            float2 v0 = make_float2(c_[mt][q][0] + bv0, c_[mt][q][1] + bv1);
            float2 v1 = make_float2(c_[mt][q][2] + bv0, c_[mt][q][3] + bv1);
            *(float2*)&Cout[(size_t)r0 * Gz + gc] = v0;
            *(float2*)&Cout[(size_t)(r0 + 8) * Gz + gc] = v1;
        }
    }
}

// ---------------- fused 2-layer persistent recurrent kernel ----------------
// Early-release pipeline: critical path = flag1 wait -> fetch h1 -> c1 MMA ->
// epilogue1 -> publish h1 -> release flag1. Layer-2 work shadows behind it.
// SMEM: Whh2 img 66560 | h1 16640 | h2 16640 | gs1 5120 | gs2 5120 = 110080 B
#define W2_OFF 0
#define H1_OFF 66560
#define H2_OFF 83200
#define GS1_OFF 99840
#define GS2_OFF 104960
#define REC_SMEM 110080
__global__ void __launch_bounds__(256, 1)
lstm_rec2(const uint32_t* __restrict__ wr1,
          const uint32_t* __restrict__ wr2,
          const __half* __restrict__ w2img,
          const float* __restrict__ xp,
          float* __restrict__ hseq)
{
    extern __shared__ __align__(16) char sm[];
    const uint32_t sbase = smem_u32(sm);
    float* gs1 = (float*)(sm + GS1_OFF);
    float* gs2 = (float*)(sm + GS2_OFF);

    const int tid  = threadIdx.x;
    const int w    = tid >> 5;
    const int lane = tid & 31;
    const int n    = blockIdx.x & 31;
    const int grp  = blockIdx.x >> 5;

    // ---- W_hh1 + W_ih2 register fragments ----
    uint32_t wB1[64], wB2[64];
    {
        const uint4* p1 = (const uint4*)(wr1 + (((size_t)n * 8 + w) * 32 + lane) * 64);
        const uint4* p2 = (const uint4*)(wr2 + (((size_t)n * 8 + w) * 32 + lane) * 64);
#pragma unroll
        for (int q = 0; q < 16; q++) {
            uint4 v1 = p1[q];
            wB1[q * 4 + 0] = v1.x; wB1[q * 4 + 1] = v1.y;
            wB1[q * 4 + 2] = v1.z; wB1[q * 4 + 3] = v1.w;
            uint4 v2 = p2[q];
            wB2[q * 4 + 0] = v2.x; wB2[q * 4 + 1] = v2.y;
            wB2[q * 4 + 2] = v2.z; wB2[q * 4 + 3] = v2.w;
        }
    }

    // ---- W_hh2 image into SMEM (one-time) ----
    {
        const char* src = (const char*)w2img + (size_t)n * (64 * K2P * 2);
        for (int z = tid; z < 4160; z += 256)
            cpa16(sbase + W2_OFF + z * 16, src + (size_t)z * 16);
        cpa_commit();
    }

    // epilogue mapping
    const int em   = tid >> 4;
    const int col  = tid & 15;
    const int gcol = n * 16 + col;
    float c1reg = 0.f, c2reg = 0.f;
    const float b2i = g_bias2[0 * Hz + gcol];
    const float b2f = g_bias2[1 * Hz + gcol];
    const float b2g = g_bias2[2 * Hz + gcol];
    const float b2o = g_bias2[3 * Hz + gcol];

    g_h1[grp][0][em * Hz + gcol] = __float2half(0.f);
    g_h2[grp][0][em * Hz + gcol] = __float2half(0.f);
    g_h2[grp][1][em * Hz + gcol] = __float2half(0.f);

    const unsigned long long base1 = g_flag1[grp][n][0];
    const unsigned long long base2 = g_flag2[grp][n][0];
    __syncthreads();
    if (tid == 0) {
        flag_release(&g_flag1[grp][n][0], base1 + 1ULL);
        flag_release(&g_flag2[grp][n][0], base2 + 1ULL);
    }

    // ldmatrix addressing (conflict-free strides)
    const uint32_t a1_base = sbase + H1_OFF + (uint32_t)((lane & 15) * HROWB + (lane >> 4) * 16);
    const uint32_t a2_base = sbase + H2_OFF + (uint32_t)((lane & 15) * HROWB + (lane >> 4) * 16);
    const uint32_t b2_base = sbase + W2_OFF +
        (uint32_t)((8 * w + (lane & 7)) * (K2P * 2) + (lane >> 3) * 16);
    const int crow = lane >> 2;
    const int sc   = (w >> 1) * 16 + (w & 1) * 8 + (lane & 3) * 2;

    for (int r = 0; r <= Tz; r++) {
        // ---- xp prefetch (issued before the barrier; DRAM latency hidden) ----
        const int tq = (r < Tz) ? r : (Tz - 1);
        const float* xb = xp + ((size_t)(grp * 16 + em) * Tz + tq) * Gz + gcol;
        float xq0 = __ldg(xb);
        float xq1 = __ldg(xb + 512);
        float xq2 = __ldg(xb + 1024);
        float xq3 = __ldg(xb + 1536);

        // ---- A: wait flag1 (h1(r-1) published by all slices) ----
        if (tid < NSLICE) {
            while (flag_acquire(&g_flag1[grp][tid][0]) < base1 + 1ULL + (unsigned long long)r) { }
        }
        __syncthreads();

        // ---- B: fetch h1(r-1) tile ----
        {
            const char* s1 = (const char*)&g_h1[grp][r & 1][0];
#pragma unroll
            for (int q = 0; q < 4; q++) {
                int z = q * 256 + tid;
                uint32_t off = (uint32_t)((z >> 6) * HROWB + (z & 63) * 16);
                cpa16(sbase + H1_OFF + off, s1 + z * 16);
            }
            cpa_commit();
        }
        cpa_wait0();
        __syncthreads();

        // ---- E: part1a — layer-1 gates only (critical) ----
        float c1_[4] = {0.f, 0.f, 0.f, 0.f};
#pragma unroll
        for (int ks = 0; ks < 32; ks++) {
            uint32_t a0, a1, a2, a3;
            ldsm4(a0, a1, a2, a3, a1_base + (uint32_t)(ks * 32));
            mma16816(c1_, a0, a1, a2, a3, wB1[2 * ks], wB1[2 * ks + 1]);
        }

        // ---- F: stage gs1 ----
        gs1[crow * 80 + sc]           = c1_[0];
        gs1[crow * 80 + sc + 1]       = c1_[1];
        gs1[(crow + 8) * 80 + sc]     = c1_[2];
        gs1[(crow + 8) * 80 + sc + 1] = c1_[3];
        __syncthreads();

        // ---- G: epilogue1, publish h1(r), release flag1 ----
        if (r < Tz) {
            float gi = gs1[em * 80 + col]      + xq0;
            float gf = gs1[em * 80 + 16 + col] + xq1;
            float gg = gs1[em * 80 + 32 + col] + xq2;
            float go = gs1[em * 80 + 48 + col] + xq3;
            float iv = sig_(gi), fv = sig_(gf), gv = tanh_(gg), ov = sig_(go);
            c1reg = fv * c1reg + iv * gv;
            float h1v = ov * tanh_(c1reg);
            g_h1[grp][(r + 1) & 1][em * Hz + gcol] = __float2half(h1v);
        }
        __syncthreads();
        if (tid == 0) flag_release(&g_flag1[grp][n][0], base1 + 2ULL + (unsigned long long)r);

        // ---- H: part1b — layer-2 ih contribution (shadow; h1 tile still valid) ----
        float c2_[4] = {0.f, 0.f, 0.f, 0.f};
#pragma unroll
        for (int ks = 0; ks < 32; ks++) {
            uint32_t a0, a1, a2, a3;
            ldsm4(a0, a1, a2, a3, a1_base + (uint32_t)(ks * 32));
            mma16816(c2_, a0, a1, a2, a3, wB2[2 * ks], wB2[2 * ks + 1]);
        }

        // ---- I: wait flag2 (one round of slack; normally instant) ----
        if (tid < NSLICE) {
            while (flag_acquire(&g_flag2[grp][tid][0]) < base2 + 1ULL + (unsigned long long)r) { }
        }
        __syncthreads();

        // ---- J: fetch h2(r-2) tile ----
        {
            const char* s2 = (const char*)&g_h2[grp][r & 1][0];
#pragma unroll
            for (int q = 0; q < 4; q++) {
                int z = q * 256 + tid;
                uint32_t off = (uint32_t)((z >> 6) * HROWB + (z & 63) * 16);
                cpa16(sbase + H2_OFF + off, s2 + z * 16);
            }
            cpa_commit();
        }
        cpa_wait0();
        __syncthreads();

        // ---- K: part2 — layer-2 hh contribution ----
#pragma unroll
        for (int ks2 = 0; ks2 < 16; ks2++) {
            uint32_t b0, b1, b2, b3;
            ldsm4(b0, b1, b2, b3, b2_base + (uint32_t)(ks2 * 64));
            uint32_t a0, a1, a2, a3;
            ldsm4(a0, a1, a2, a3, a2_base + (uint32_t)((2 * ks2) * 32));
            mma16816(c2_, a0, a1, a2, a3, b0, b1);
            ldsm4(a0, a1, a2, a3, a2_base + (uint32_t)((2 * ks2 + 1) * 32));
            mma16816(c2_, a0, a1, a2, a3, b2, b3);
        }

        // ---- L: stage gs2 ----
        gs2[crow * 80 + sc]           = c2_[0];
        gs2[crow * 80 + sc + 1]       = c2_[1];
        gs2[(crow + 8) * 80 + sc]     = c2_[2];
        gs2[(crow + 8) * 80 + sc + 1] = c2_[3];
        __syncthreads();

        // ---- M: epilogue2, publish h2(r-1), release flag2 ----
        float h2v = 0.f;
        const bool do2 = (r > 0);
        if (do2) {
            float gi = gs2[em * 80 + col]      + b2i;
            float gf = gs2[em * 80 + 16 + col] + b2f;
            float gg = gs2[em * 80 + 32 + col] + b2g;
            float go = gs2[em * 80 + 48 + col] + b2o;
            float iv = sig_(gi), fv = sig_(gf), gv = tanh_(gg), ov = sig_(go);
            c2reg = fv * c2reg + iv * gv;
            h2v = ov * tanh_(c2reg);
            g_h2[grp][(r + 1) & 1][em * Hz + gcol] = __float2half(h2v);
        }
        __syncthreads();
        if (tid == 0) flag_release(&g_flag2[grp][n][0], base2 + 2ULL + (unsigned long long)r);

        // ---- N: output store (off critical path) ----
        if (do2)
            hseq[((size_t)(grp * 16 + em) * Tz + (r - 1)) * Hz + gcol] = h2v;
    }
}

// ---------------- final transpose: hseq [b][t][c] -> out [b][c][t] ----------
__global__ void __launch_bounds__(256)
transpose_out(const float* __restrict__ hseq, float* __restrict__ out)
{
    __shared__ float smt[32][33];
    const int t0 = blockIdx.x * 32;
    const int c0 = blockIdx.y * 32;
    const int b  = blockIdx.z;
    const int tx = threadIdx.x;
    const int ty = threadIdx.y;

#pragma unroll
    for (int i = 0; i < 4; i++)
        smt[ty + i * 8][tx] = hseq[((size_t)b * Tz + t0 + ty + i * 8) * Hz + c0 + tx];
    __syncthreads();
#pragma unroll
    for (int i = 0; i < 4; i++)
        out[(size_t)b * (Hz * Tz) + (size_t)(c0 + ty + i * 8) * Tz + t0 + tx] = smt[tx][ty + i * 8];
}

// ---------------- host launcher ----------------
extern "C" void kernel_launch(void* const* d_in, const int* in_sizes, int n_in,
                              void* d_out, int out_size)
{
    const float* x     = (const float*)d_in[0];
    const float* W_ih1 = (const float*)d_in[1];
    const float* W_hh1 = (const float*)d_in[2];
    const float* b_ih1 = (const float*)d_in[3];
    const float* b_hh1 = (const float*)d_in[4];
    const float* W_ih2 = (const float*)d_in[5];
    const float* W_hh2 = (const float*)d_in[6];
    const float* b_ih2 = (const float*)d_in[7];
    const float* b_hh2 = (const float*)d_in[8];
    float* out = (float*)d_out;

    float *p_xp, *p_hseq, *p_b1;
    __half *p_xh, *p_w16a, *p_w2img;
    uint32_t *p_wr1, *p_wr2;
    cudaGetSymbolAddress((void**)&p_xp,    g_xp);
    cudaGetSymbolAddress((void**)&p_hseq,  g_hseq);
    cudaGetSymbolAddress((void**)&p_xh,    g_xh);
    cudaGetSymbolAddress((void**)&p_w16a,  g_w16a);
    cudaGetSymbolAddress((void**)&p_b1,    g_bias1);
    cudaGetSymbolAddress((void**)&p_wr1,   g_wr1);
    cudaGetSymbolAddress((void**)&p_wr2,   g_wr2);
    cudaGetSymbolAddress((void**)&p_w2img, g_w2img);

    cudaFuncSetAttribute(lstm_rec2, cudaFuncAttributeMaxDynamicSharedMemorySize, REC_SMEM);

    // prep
    lstm_prep<<<(Gz * Cz + 255) / 256, 256>>>(W_ih1, b_ih1, b_hh1, b_ih2, b_hh2);
    prep_wr<<<(2 * NSLICE * 8 * 32 * 32 + 255) / 256, 256>>>(W_hh1, W_ih2);
    prep_w2img<<<(NSLICE * 64 * 512 + 255) / 256, 256>>>(W_hh2);
    convert_x<<<dim3(Tz / 32, Cz / 32, Bz), dim3(32, 8)>>>(x, p_xh);

    // xp1 = x16 @ W_ih1^T + bias1
    gemm_xp16<<<dim3(Gz / 128, Mz / 128), 256>>>(p_xh, p_w16a, p_b1, p_xp);

    // fused 2-layer recurrence -> g_hseq [m][c]
    lstm_rec2<<<NGRP * NSLICE, 256, REC_SMEM>>>(p_wr1, p_wr2, p_w2img, p_xp, p_hseq);

    // final transpose -> out (B, H, T)
    transpose_out<<<dim3(Tz / 32, Hz / 32, Bz), dim3(32, 8)>>>(p_hseq, out);
}

// round 13
// speedup vs baseline: 1.2580x; 1.2580x over previous
#include <cuda_runtime.h>
#include <cuda_fp16.h>
#include <math.h>
#include <stdint.h>

// Problem constants
#define Bz 64
#define Tz 512
#define Cz 512
#define Hz 512
#define Gz 2048    // 4*H
#define Mz (Bz*Tz) // 32768
#define NSLICE 32  // h-col slices (CTAs per group)
#define NGRP 4     // batch groups (16 rows each)
#define K2P 520    // W_hh2 image row stride (halves) -> 1040 B, conflict-free
#define HROWB 1040 // h tile row stride (bytes), conflict-free

// ---------------- device scratch (static, no allocation) ----------------
__device__ float g_xp[(size_t)Mz * Gz];      // [m][g]
__device__ float g_hseq[(size_t)Mz * Hz];    // [m][c]
__device__ __half g_xh[(size_t)Mz * Cz];     // fp16 x [m][c]
__device__ __half g_w16a[Gz * Cz];           // W_ih1 fp16 [g][k]
__device__ float g_bias1[Gz];
__device__ float g_bias2[Gz];
__device__ uint32_t g_wr1[NSLICE * 8 * 32 * 64];      // W_hh1 B-fragments
__device__ uint32_t g_wr2[NSLICE * 8 * 32 * 64];      // W_ih2 B-fragments
__device__ __half g_w2img[(size_t)NSLICE * 64 * K2P]; // per-slice W_hh2 images
__device__ __half g_h1[NGRP][2][16 * Hz];    // h1 fp16 double buffer
__device__ __half g_h2[NGRP][2][16 * Hz];    // h2 fp16 double buffer
__device__ unsigned long long g_flag[NGRP][NSLICE][16];  // padded flags (128B)

// ==================== helpers ====================
__device__ __forceinline__ uint32_t smem_u32(const void* p) {
    uint32_t a;
    asm("{ .reg .u64 t; cvta.to.shared.u64 t, %1; cvt.u32.u64 %0, t; }" : "=r"(a) : "l"(p));
    return a;
}
__device__ __forceinline__ void cpa16(uint32_t dst_smem, const void* src) {
    asm volatile("cp.async.cg.shared.global [%0], [%1], 16;" :: "r"(dst_smem), "l"(src));
}
__device__ __forceinline__ void cpa_commit() { asm volatile("cp.async.commit_group;"); }
__device__ __forceinline__ void cpa_wait0()  { asm volatile("cp.async.wait_group 0;" ::: "memory"); }
__device__ __forceinline__ void cpa_wait1()  { asm volatile("cp.async.wait_group 1;" ::: "memory"); }

__device__ __forceinline__ void flag_release(unsigned long long* p, unsigned long long v) {
    asm volatile("st.release.gpu.global.u64 [%0], %1;" :: "l"(p), "l"(v) : "memory");
}
__device__ __forceinline__ unsigned long long flag_acquire(const unsigned long long* p) {
    unsigned long long v;
    asm volatile("ld.acquire.gpu.global.u64 %0, [%1];" : "=l"(v) : "l"(p) : "memory");
    return v;
}

__device__ __forceinline__ void mma16816(float* c,
    uint32_t a0, uint32_t a1, uint32_t a2, uint32_t a3, uint32_t b0, uint32_t b1)
{
    asm volatile(
        "mma.sync.aligned.m16n8k16.row.col.f32.f16.f16.f32 "
        "{%0,%1,%2,%3}, {%4,%5,%6,%7}, {%8,%9}, {%0,%1,%2,%3};"
        : "+f"(c[0]), "+f"(c[1]), "+f"(c[2]), "+f"(c[3])
        : "r"(a0), "r"(a1), "r"(a2), "r"(a3), "r"(b0), "r"(b1));
}

__device__ __forceinline__ void ldsm4(uint32_t& a0, uint32_t& a1, uint32_t& a2, uint32_t& a3,
                                      uint32_t addr)
{
    asm volatile("ldmatrix.sync.aligned.m8n8.x4.shared.b16 {%0,%1,%2,%3}, [%4];"
                 : "=r"(a0), "=r"(a1), "=r"(a2), "=r"(a3) : "r"(addr));
}

__device__ __forceinline__ float sig_(float x)  { return __fdividef(1.f, 1.f + __expf(-x)); }
__device__ __forceinline__ float tanh_(float x) { return 1.f - 2.f * __fdividef(1.f, __expf(2.f * x) + 1.f); }

// ---------------- prep: fp16 W_ih1, fold biases ----------------
__global__ void lstm_prep(const float* __restrict__ Wih1,
                          const float* __restrict__ bih1,
                          const float* __restrict__ bhh1,
                          const float* __restrict__ bih2,
                          const float* __restrict__ bhh2)
{
    int i = blockIdx.x * blockDim.x + threadIdx.x;
    if (i < Gz * Cz) g_w16a[i] = __float2half(Wih1[i]);
    if (i < Gz) {
        g_bias1[i] = bih1[i] + bhh1[i];
        g_bias2[i] = bih2[i] + bhh2[i];
    }
}

// ---------------- prep: W_hh1 / W_ih2 -> mma.sync B fragments ----------------
__global__ void prep_wr(const float* __restrict__ Whh1, const float* __restrict__ Wih2)
{
    int e = blockIdx.x * blockDim.x + threadIdx.x;
    if (e >= 2 * NSLICE * 8 * 32 * 32) return;
    int ks   = e & 31;
    int lane = (e >> 5) & 31;
    int w    = (e >> 10) & 7;
    int n    = (e >> 13) & 31;
    int l    = e >> 18;
    const float* W = l ? Wih2 : Whh1;
    int wrow = (w >> 1) * Hz + n * 16 + (w & 1) * 8 + (lane >> 2);
    int kb   = ks * 16 + (lane & 3) * 2;
    const float* r = W + (size_t)wrow * Hz;
    __half2 v0 = __floats2half2_rn(r[kb],     r[kb + 1]);
    __half2 v1 = __floats2half2_rn(r[kb + 8], r[kb + 9]);
    uint32_t* dst = l ? g_wr2 : g_wr1;
    size_t idx = ((((size_t)n * 8 + w) * 32 + lane) * 32 + ks) * 2;
    dst[idx]     = *(const uint32_t*)&v0;
    dst[idx + 1] = *(const uint32_t*)&v1;
}

// ---------------- prep: W_hh2 per-slice fp16 image (stride K2P) -----------
__global__ void prep_w2img(const float* __restrict__ Whh2)
{
    int e = blockIdx.x * blockDim.x + threadIdx.x;   // [n][q][k]
    if (e >= NSLICE * 64 * 512) return;
    int k = e & 511;
    int q = (e >> 9) & 63;
    int n = e >> 15;
    int row = (q >> 4) * Hz + n * 16 + (q & 15);
    g_w2img[((size_t)n * 64 + q) * K2P + k] = __float2half(Whh2[(size_t)row * Hz + k]);
}

// ---------------- convert x (B,C,T) -> fp16 [b*T+t][c] ----------------
__global__ void __launch_bounds__(256)
convert_x(const float* __restrict__ x, __half* __restrict__ xh)
{
    __shared__ float smt[32][33];
    const int t0 = blockIdx.x * 32;
    const int c0 = blockIdx.y * 32;
    const int b  = blockIdx.z;
    const int tx = threadIdx.x;
    const int ty = threadIdx.y;
#pragma unroll
    for (int i = 0; i < 4; i++)
        smt[ty + i * 8][tx] = x[(size_t)b * (Cz * Tz) + (size_t)(c0 + ty + i * 8) * Tz + t0 + tx];
    __syncthreads();
#pragma unroll
    for (int i = 0; i < 4; i++)
        xh[((size_t)b * Tz + t0 + ty + i * 8) * Cz + c0 + tx] = __float2half(smt[tx][ty + i * 8]);
}

// ---------------- fp16 tensor-core xp GEMM (layer 1 only) ----------------
#define BKP 40
#define ASZ (128 * BKP * 2)
__global__ void __launch_bounds__(256)
gemm_xp16(const __half* __restrict__ A,
          const __half* __restrict__ Bw,
          const float* __restrict__ bias,
          float* __restrict__ Cout)
{
    __shared__ __half sbuf[2 * 2 * 128 * BKP];
    const uint32_t s0 = smem_u32(sbuf);

    const int m0 = blockIdx.y * 128;
    const int g0 = blockIdx.x * 128;
    const int tid = threadIdx.x;
    const int w = tid >> 5;
    const int lane = tid & 31;
    const int wm = (w >> 1) * 32;
    const int wn = (w & 1) * 64;

    float c_[2][8][4];
#pragma unroll
    for (int mt = 0; mt < 2; mt++)
#pragma unroll
        for (int q = 0; q < 8; q++)
#pragma unroll
            for (int i = 0; i < 4; i++) c_[mt][q][i] = 0.f;

    const int zr0 = tid >> 2, zs0 = tid & 3;
    const int zr1 = (tid + 256) >> 2, zs1 = tid & 3;

    const uint32_t a_off = (uint32_t)(((wm + (lane & 15)) * BKP + (lane >> 4) * 8) * 2);
    const uint32_t b_off = (uint32_t)(((wn + ((lane >> 4) & 1) * 8 + (lane & 7)) * BKP
                                      + ((lane >> 3) & 1) * 8) * 2);

    {
        cpa16(s0 + (zr0 * BKP + zs0 * 8) * 2, A + (size_t)(m0 + zr0) * Cz + zs0 * 8);
        cpa16(s0 + (zr1 * BKP + zs1 * 8) * 2, A + (size_t)(m0 + zr1) * Cz + zs1 * 8);
        cpa16(s0 + 2 * ASZ + (zr0 * BKP + zs0 * 8) * 2, Bw + (size_t)(g0 + zr0) * Cz + zs0 * 8);
        cpa16(s0 + 2 * ASZ + (zr1 * BKP + zs1 * 8) * 2, Bw + (size_t)(g0 + zr1) * Cz + zs1 * 8);
        cpa_commit();
    }

    for (int c = 0; c < 16; c++) {
        const int buf = c & 1;
        if (c < 15) {
            const int nb = buf ^ 1;
            const int k0 = (c + 1) * 32;
            cpa16(s0 + nb * ASZ + (zr0 * BKP + zs0 * 8) * 2,
                  A + (size_t)(m0 + zr0) * Cz + k0 + zs0 * 8);
            cpa16(s0 + nb * ASZ + (zr1 * BKP + zs1 * 8) * 2,
                  A + (size_t)(m0 + zr1) * Cz + k0 + zs1 * 8);
            cpa16(s0 + (2 + nb) * ASZ + (zr0 * BKP + zs0 * 8) * 2,
                  Bw + (size_t)(g0 + zr0) * Cz + k0 + zs0 * 8);
            cpa16(s0 + (2 + nb) * ASZ + (zr1 * BKP + zs1 * 8) * 2,
                  Bw + (size_t)(g0 + zr1) * Cz + k0 + zs1 * 8);
            cpa_commit();
            cpa_wait1();
        } else {
            cpa_wait0();
        }
        __syncthreads();

        const uint32_t ab = s0 + buf * ASZ + a_off;
        const uint32_t bb = s0 + (2 + buf) * ASZ + b_off;
#pragma unroll
        for (int ks = 0; ks < 2; ks++) {
            uint32_t a[2][4];
#pragma unroll
            for (int mt = 0; mt < 2; mt++)
                ldsm4(a[mt][0], a[mt][1], a[mt][2], a[mt][3],
                      ab + (uint32_t)(mt * 16 * BKP * 2 + ks * 32));
#pragma unroll
            for (int j = 0; j < 4; j++) {
                uint32_t r0, r1, r2, r3;
                ldsm4(r0, r1, r2, r3, bb + (uint32_t)(j * 16 * BKP * 2 + ks * 32));
                mma16816(c_[0][2 * j],     a[0][0], a[0][1], a[0][2], a[0][3], r0, r1);
                mma16816(c_[1][2 * j],     a[1][0], a[1][1], a[1][2], a[1][3], r0, r1);
                mma16816(c_[0][2 * j + 1], a[0][0], a[0][1], a[0][2], a[0][3], r2, r3);
                mma16816(c_[1][2 * j + 1], a[1][0], a[1][1], a[1][2], a[1][3], r2, r3);
            }
        }
        __syncthreads();
    }

#pragma unroll
    for (int q = 0; q < 8; q++) {
        const int gc = g0 + wn + q * 8 + (lane & 3) * 2;
        const float bv0 = bias[gc];
        const float bv1 = bias[gc + 1];
#pragma unroll
        for (int mt = 0; mt < 2; mt++) {
            const int r0 = m0 + wm + mt * 16 + (lane >> 2);
            float2 v0 = make_float2(c_[mt][q][0] + bv0, c_[mt][q][1] + bv1);
            float2 v1 = make_float2(c_[mt][q][2] + bv0, c_[mt][q][3] + bv1);
            *(float2*)&Cout[(size_t)r0 * Gz + gc] = v0;
            *(float2*)&Cout[(size_t)(r0 + 8) * Gz + gc] = v1;
        }
    }
}

// ---------------- fused 2-layer persistent recurrent kernel (R11 + tweaks) --
// SMEM: Whh2 img 66560 | h1 16640 | h2 16640 | gs1 5120 | gs2 5120 = 110080 B
#define W2_OFF 0
#define H1_OFF 66560
#define H2_OFF 83200
#define GS1_OFF 99840
#define GS2_OFF 104960
#define REC_SMEM 110080
__global__ void __launch_bounds__(256, 1)
lstm_rec2(const uint32_t* __restrict__ wr1,
          const uint32_t* __restrict__ wr2,
          const __half* __restrict__ w2img,
          const float* __restrict__ xp,
          float* __restrict__ hseq)
{
    extern __shared__ __align__(16) char sm[];
    const uint32_t sbase = smem_u32(sm);
    float* gs1 = (float*)(sm + GS1_OFF);
    float* gs2 = (float*)(sm + GS2_OFF);

    const int tid  = threadIdx.x;
    const int w    = tid >> 5;
    const int lane = tid & 31;
    const int n    = blockIdx.x & 31;
    const int grp  = blockIdx.x >> 5;

    // ---- W_hh1 + W_ih2 register fragments ----
    uint32_t wB1[64], wB2[64];
    {
        const uint4* p1 = (const uint4*)(wr1 + (((size_t)n * 8 + w) * 32 + lane) * 64);
        const uint4* p2 = (const uint4*)(wr2 + (((size_t)n * 8 + w) * 32 + lane) * 64);
#pragma unroll
        for (int q = 0; q < 16; q++) {
            uint4 v1 = p1[q];
            wB1[q * 4 + 0] = v1.x; wB1[q * 4 + 1] = v1.y;
            wB1[q * 4 + 2] = v1.z; wB1[q * 4 + 3] = v1.w;
            uint4 v2 = p2[q];
            wB2[q * 4 + 0] = v2.x; wB2[q * 4 + 1] = v2.y;
            wB2[q * 4 + 2] = v2.z; wB2[q * 4 + 3] = v2.w;
        }
    }

    // ---- W_hh2 image into SMEM (one-time) ----
    {
        const char* src = (const char*)w2img + (size_t)n * (64 * K2P * 2);
        for (int z = tid; z < 4160; z += 256)
            cpa16(sbase + W2_OFF + z * 16, src + (size_t)z * 16);
        cpa_commit();
    }

    // epilogue mapping
    const int em   = tid >> 4;
    const int col  = tid & 15;
    const int gcol = n * 16 + col;
    float c1reg = 0.f, c2reg = 0.f;
    const float b2i = g_bias2[0 * Hz + gcol];
    const float b2f = g_bias2[1 * Hz + gcol];
    const float b2g = g_bias2[2 * Hz + gcol];
    const float b2o = g_bias2[3 * Hz + gcol];

    g_h1[grp][0][em * Hz + gcol] = __float2half(0.f);
    g_h2[grp][0][em * Hz + gcol] = __float2half(0.f);
    g_h2[grp][1][em * Hz + gcol] = __float2half(0.f);

    const unsigned long long base = g_flag[grp][n][0];
    __syncthreads();
    if (tid == 0) flag_release(&g_flag[grp][n][0], base + 1ULL);

    // ldmatrix addressing (conflict-free strides)
    const uint32_t a1_base = sbase + H1_OFF + (uint32_t)((lane & 15) * HROWB + (lane >> 4) * 16);
    const uint32_t a2_base = sbase + H2_OFF + (uint32_t)((lane & 15) * HROWB + (lane >> 4) * 16);
    const uint32_t b2_base = sbase + W2_OFF +
        (uint32_t)((8 * w + (lane & 7)) * (K2P * 2) + (lane >> 3) * 16);
    const int crow = lane >> 2;
    const int sc   = (w >> 1) * 16 + (w & 1) * 8 + (lane & 3) * 2;

    for (int r = 0; r <= Tz; r++) {
        // ---- xp prefetch BEFORE the barrier (DRAM latency hidden) ----
        const int tq = (r < Tz) ? r : (Tz - 1);
        const float* xb = xp + ((size_t)(grp * 16 + em) * Tz + tq) * Gz + gcol;
        float xq0 = __ldg(xb);
        float xq1 = __ldg(xb + 512);
        float xq2 = __ldg(xb + 1024);
        float xq3 = __ldg(xb + 1536);

        // ---- barrier: all slices finished round r-1 ----
        if (tid < NSLICE) {
            while (flag_acquire(&g_flag[grp][tid][0]) < base + 1ULL + (unsigned long long)r) { }
        }
        __syncthreads();

        // ---- cp.async h1(r-1) [group A], then h2(r-2) [group B] ----
        {
            const char* s1 = (const char*)&g_h1[grp][r & 1][0];
            const char* s2 = (const char*)&g_h2[grp][r & 1][0];
#pragma unroll
            for (int q = 0; q < 4; q++) {
                int z = q * 256 + tid;
                uint32_t off = (uint32_t)((z >> 6) * HROWB + (z & 63) * 16);
                cpa16(sbase + H1_OFF + off, s1 + z * 16);
            }
            cpa_commit();
#pragma unroll
            for (int q = 0; q < 4; q++) {
                int z = q * 256 + tid;
                uint32_t off = (uint32_t)((z >> 6) * HROWB + (z & 63) * 16);
                cpa16(sbase + H2_OFF + off, s2 + z * 16);
            }
            cpa_commit();
        }

        // ---- wait h1 only; part1 overlaps the h2 fetch ----
        cpa_wait1();
        __syncthreads();

        float c1_[4] = {0.f, 0.f, 0.f, 0.f};
        float c2_[4] = {0.f, 0.f, 0.f, 0.f};

        // part 1: A = h1(r-1); layer-1 (wB1) and layer-2-ih (wB2) from regs
#pragma unroll
        for (int ks = 0; ks < 32; ks++) {
            uint32_t a0, a1, a2, a3;
            ldsm4(a0, a1, a2, a3, a1_base + (uint32_t)(ks * 32));
            mma16816(c1_, a0, a1, a2, a3, wB1[2 * ks], wB1[2 * ks + 1]);
            mma16816(c2_, a0, a1, a2, a3, wB2[2 * ks], wB2[2 * ks + 1]);
        }

        // ---- wait h2; part2 ----
        cpa_wait0();
        __syncthreads();

#pragma unroll
        for (int ks2 = 0; ks2 < 16; ks2++) {
            uint32_t b0, b1, b2, b3;
            ldsm4(b0, b1, b2, b3, b2_base + (uint32_t)(ks2 * 64));
            uint32_t a0, a1, a2, a3;
            ldsm4(a0, a1, a2, a3, a2_base + (uint32_t)((2 * ks2) * 32));
            mma16816(c2_, a0, a1, a2, a3, b0, b1);
            ldsm4(a0, a1, a2, a3, a2_base + (uint32_t)((2 * ks2 + 1) * 32));
            mma16816(c2_, a0, a1, a2, a3, b2, b3);
        }

        // ---- stage gates (one sync for both) ----
        gs1[crow * 80 + sc]           = c1_[0];
        gs1[crow * 80 + sc + 1]       = c1_[1];
        gs1[(crow + 8) * 80 + sc]     = c1_[2];
        gs1[(crow + 8) * 80 + sc + 1] = c1_[3];
        gs2[crow * 80 + sc]           = c2_[0];
        gs2[crow * 80 + sc + 1]       = c2_[1];
        gs2[(crow + 8) * 80 + sc]     = c2_[2];
        gs2[(crow + 8) * 80 + sc + 1] = c2_[3];
        __syncthreads();

        // ---- epilogues ----
        float h2v = 0.f;
        const bool do2 = (r > 0);
        if (r < Tz) {
            float gi = gs1[em * 80 + col]      + xq0;
            float gf = gs1[em * 80 + 16 + col] + xq1;
            float gg = gs1[em * 80 + 32 + col] + xq2;
            float go = gs1[em * 80 + 48 + col] + xq3;
            float iv = sig_(gi), fv = sig_(gf), gv = tanh_(gg), ov = sig_(go);
            c1reg = fv * c1reg + iv * gv;
            float h1v = ov * tanh_(c1reg);
            g_h1[grp][(r + 1) & 1][em * Hz + gcol] = __float2half(h1v);
        }
        if (do2) {
            float gi = gs2[em * 80 + col]      + b2i;
            float gf = gs2[em * 80 + 16 + col] + b2f;
            float gg = gs2[em * 80 + 32 + col] + b2g;
            float go = gs2[em * 80 + 48 + col] + b2o;
            float iv = sig_(gi), fv = sig_(gf), gv = tanh_(gg), ov = sig_(go);
            c2reg = fv * c2reg + iv * gv;
            h2v = ov * tanh_(c2reg);
            g_h2[grp][(r + 1) & 1][em * Hz + gcol] = __float2half(h2v);
        }
        __syncthreads();
        if (tid == 0) flag_release(&g_flag[grp][n][0], base + 2ULL + (unsigned long long)r);
        if (do2)
            hseq[((size_t)(grp * 16 + em) * Tz + (r - 1)) * Hz + gcol] = h2v;
    }
}

// ---------------- final transpose: hseq [b][t][c] -> out [b][c][t] ----------
__global__ void __launch_bounds__(256)
transpose_out(const float* __restrict__ hseq, float* __restrict__ out)
{
    __shared__ float smt[32][33];
    const int t0 = blockIdx.x * 32;
    const int c0 = blockIdx.y * 32;
    const int b  = blockIdx.z;
    const int tx = threadIdx.x;
    const int ty = threadIdx.y;

#pragma unroll
    for (int i = 0; i < 4; i++)
        smt[ty + i * 8][tx] = hseq[((size_t)b * Tz + t0 + ty + i * 8) * Hz + c0 + tx];
    __syncthreads();
#pragma unroll
    for (int i = 0; i < 4; i++)
        out[(size_t)b * (Hz * Tz) + (size_t)(c0 + ty + i * 8) * Tz + t0 + tx] = smt[tx][ty + i * 8];
}

// ---------------- host launcher ----------------
extern "C" void kernel_launch(void* const* d_in, const int* in_sizes, int n_in,
                              void* d_out, int out_size)
{
    const float* x     = (const float*)d_in[0];
    const float* W_ih1 = (const float*)d_in[1];
    const float* W_hh1 = (const float*)d_in[2];
    const float* b_ih1 = (const float*)d_in[3];
    const float* b_hh1 = (const float*)d_in[4];
    const float* W_ih2 = (const float*)d_in[5];
    const float* W_hh2 = (const float*)d_in[6];
    const float* b_ih2 = (const float*)d_in[7];
    const float* b_hh2 = (const float*)d_in[8];
    float* out = (float*)d_out;

    float *p_xp, *p_hseq, *p_b1;
    __half *p_xh, *p_w16a, *p_w2img;
    uint32_t *p_wr1, *p_wr2;
    cudaGetSymbolAddress((void**)&p_xp,    g_xp);
    cudaGetSymbolAddress((void**)&p_hseq,  g_hseq);
    cudaGetSymbolAddress((void**)&p_xh,    g_xh);
    cudaGetSymbolAddress((void**)&p_w16a,  g_w16a);
    cudaGetSymbolAddress((void**)&p_b1,    g_bias1);
    cudaGetSymbolAddress((void**)&p_wr1,   g_wr1);
    cudaGetSymbolAddress((void**)&p_wr2,   g_wr2);
    cudaGetSymbolAddress((void**)&p_w2img, g_w2img);

    cudaFuncSetAttribute(lstm_rec2, cudaFuncAttributeMaxDynamicSharedMemorySize, REC_SMEM);

    // prep
    lstm_prep<<<(Gz * Cz + 255) / 256, 256>>>(W_ih1, b_ih1, b_hh1, b_ih2, b_hh2);
    prep_wr<<<(2 * NSLICE * 8 * 32 * 32 + 255) / 256, 256>>>(W_hh1, W_ih2);
    prep_w2img<<<(NSLICE * 64 * 512 + 255) / 256, 256>>>(W_hh2);
    convert_x<<<dim3(Tz / 32, Cz / 32, Bz), dim3(32, 8)>>>(x, p_xh);

    // xp1 = x16 @ W_ih1^T + bias1
    gemm_xp16<<<dim3(Gz / 128, Mz / 128), 256>>>(p_xh, p_w16a, p_b1, p_xp);

    // fused 2-layer recurrence -> g_hseq [m][c]
    lstm_rec2<<<NGRP * NSLICE, 256, REC_SMEM>>>(p_wr1, p_wr2, p_w2img, p_xp, p_hseq);

    // final transpose -> out (B, H, T)
    transpose_out<<<dim3(Tz / 32, Hz / 32, Bz), dim3(32, 8)>>>(p_hseq, out);
}

// round 14
// speedup vs baseline: 1.2766x; 1.0147x over previous
#include <cuda_runtime.h>
#include <cuda_fp16.h>
#include <math.h>
#include <stdint.h>

// Problem constants
#define Bz 64
#define Tz 512
#define Cz 512
#define Hz 512
#define Gz 2048    // 4*H
#define Mz (Bz*Tz) // 32768
#define NSLICE 32  // h-col slices (CTAs per group)
#define NGRP 4     // batch groups (16 rows each)
#define K2P 520    // W_hh2 image row stride (halves) -> 1040 B, conflict-free
#define HROWB 1040 // h tile row stride (bytes), conflict-free

// ---------------- device scratch (static, no allocation) ----------------
__device__ float g_xp[(size_t)Mz * Gz];      // [m][g]
__device__ float g_hseq[(size_t)Mz * Hz];    // [m][c]
__device__ __half g_xh[(size_t)Mz * Cz];     // fp16 x [m][c]
__device__ __half g_w16a[Gz * Cz];           // W_ih1 fp16 [g][k]
__device__ float g_bias1[Gz];
__device__ float g_bias2[Gz];
__device__ uint32_t g_wr1[NSLICE * 8 * 32 * 64];      // W_hh1 B-fragments
__device__ uint32_t g_wr2[NSLICE * 8 * 32 * 64];      // W_ih2 B-fragments
__device__ __half g_w2img[(size_t)NSLICE * 64 * K2P]; // per-slice W_hh2 images
__device__ __half g_h1[NGRP][2][16 * Hz];    // h1 fp16 double buffer
__device__ __half g_h2[NGRP][2][16 * Hz];    // h2 fp16 double buffer
__device__ unsigned long long g_flag1[NGRP][NSLICE][16];  // h1-ready flags (128B pad)
__device__ unsigned long long g_flag2[NGRP][NSLICE][16];  // h2-ready flags (128B pad)

// ==================== helpers ====================
__device__ __forceinline__ uint32_t smem_u32(const void* p) {
    uint32_t a;
    asm("{ .reg .u64 t; cvta.to.shared.u64 t, %1; cvt.u32.u64 %0, t; }" : "=r"(a) : "l"(p));
    return a;
}
__device__ __forceinline__ void cpa16(uint32_t dst_smem, const void* src) {
    asm volatile("cp.async.cg.shared.global [%0], [%1], 16;" :: "r"(dst_smem), "l"(src));
}
__device__ __forceinline__ void cpa_commit() { asm volatile("cp.async.commit_group;"); }
__device__ __forceinline__ void cpa_wait0()  { asm volatile("cp.async.wait_group 0;" ::: "memory"); }
__device__ __forceinline__ void cpa_wait1()  { asm volatile("cp.async.wait_group 1;" ::: "memory"); }

__device__ __forceinline__ void flag_release(unsigned long long* p, unsigned long long v) {
    asm volatile("st.release.gpu.global.u64 [%0], %1;" :: "l"(p), "l"(v) : "memory");
}
__device__ __forceinline__ unsigned long long flag_acquire(const unsigned long long* p) {
    unsigned long long v;
    asm volatile("ld.acquire.gpu.global.u64 %0, [%1];" : "=l"(v) : "l"(p) : "memory");
    return v;
}

__device__ __forceinline__ void mma16816(float* c,
    uint32_t a0, uint32_t a1, uint32_t a2, uint32_t a3, uint32_t b0, uint32_t b1)
{
    asm volatile(
        "mma.sync.aligned.m16n8k16.row.col.f32.f16.f16.f32 "
        "{%0,%1,%2,%3}, {%4,%5,%6,%7}, {%8,%9}, {%0,%1,%2,%3};"
        : "+f"(c[0]), "+f"(c[1]), "+f"(c[2]), "+f"(c[3])
        : "r"(a0), "r"(a1), "r"(a2), "r"(a3), "r"(b0), "r"(b1));
}

__device__ __forceinline__ void ldsm4(uint32_t& a0, uint32_t& a1, uint32_t& a2, uint32_t& a3,
                                      uint32_t addr)
{
    asm volatile("ldmatrix.sync.aligned.m8n8.x4.shared.b16 {%0,%1,%2,%3}, [%4];"
                 : "=r"(a0), "=r"(a1), "=r"(a2), "=r"(a3) : "r"(addr));
}

__device__ __forceinline__ float sig_(float x)  { return __fdividef(1.f, 1.f + __expf(-x)); }
__device__ __forceinline__ float tanh_(float x) { return 1.f - 2.f * __fdividef(1.f, __expf(2.f * x) + 1.f); }

// ---------------- prep: fp16 W_ih1, fold biases ----------------
__global__ void lstm_prep(const float* __restrict__ Wih1,
                          const float* __restrict__ bih1,
                          const float* __restrict__ bhh1,
                          const float* __restrict__ bih2,
                          const float* __restrict__ bhh2)
{
    int i = blockIdx.x * blockDim.x + threadIdx.x;
    if (i < Gz * Cz) g_w16a[i] = __float2half(Wih1[i]);
    if (i < Gz) {
        g_bias1[i] = bih1[i] + bhh1[i];
        g_bias2[i] = bih2[i] + bhh2[i];
    }
}

// ---------------- prep: W_hh1 / W_ih2 -> mma.sync B fragments ----------------
__global__ void prep_wr(const float* __restrict__ Whh1, const float* __restrict__ Wih2)
{
    int e = blockIdx.x * blockDim.x + threadIdx.x;
    if (e >= 2 * NSLICE * 8 * 32 * 32) return;
    int ks   = e & 31;
    int lane = (e >> 5) & 31;
    int w    = (e >> 10) & 7;
    int n    = (e >> 13) & 31;
    int l    = e >> 18;
    const float* W = l ? Wih2 : Whh1;
    int wrow = (w >> 1) * Hz + n * 16 + (w & 1) * 8 + (lane >> 2);
    int kb   = ks * 16 + (lane & 3) * 2;
    const float* r = W + (size_t)wrow * Hz;
    __half2 v0 = __floats2half2_rn(r[kb],     r[kb + 1]);
    __half2 v1 = __floats2half2_rn(r[kb + 8], r[kb + 9]);
    uint32_t* dst = l ? g_wr2 : g_wr1;
    size_t idx = ((((size_t)n * 8 + w) * 32 + lane) * 32 + ks) * 2;
    dst[idx]     = *(const uint32_t*)&v0;
    dst[idx + 1] = *(const uint32_t*)&v1;
}

// ---------------- prep: W_hh2 per-slice fp16 image (stride K2P) -----------
__global__ void prep_w2img(const float* __restrict__ Whh2)
{
    int e = blockIdx.x * blockDim.x + threadIdx.x;   // [n][q][k]
    if (e >= NSLICE * 64 * 512) return;
    int k = e & 511;
    int q = (e >> 9) & 63;
    int n = e >> 15;
    int row = (q >> 4) * Hz + n * 16 + (q & 15);
    g_w2img[((size_t)n * 64 + q) * K2P + k] = __float2half(Whh2[(size_t)row * Hz + k]);
}

// ---------------- convert x (B,C,T) -> fp16 [b*T+t][c] ----------------
__global__ void __launch_bounds__(256)
convert_x(const float* __restrict__ x, __half* __restrict__ xh)
{
    __shared__ float smt[32][33];
    const int t0 = blockIdx.x * 32;
    const int c0 = blockIdx.y * 32;
    const int b  = blockIdx.z;
    const int tx = threadIdx.x;
    const int ty = threadIdx.y;
#pragma unroll
    for (int i = 0; i < 4; i++)
        smt[ty + i * 8][tx] = x[(size_t)b * (Cz * Tz) + (size_t)(c0 + ty + i * 8) * Tz + t0 + tx];
    __syncthreads();
#pragma unroll
    for (int i = 0; i < 4; i++)
        xh[((size_t)b * Tz + t0 + ty + i * 8) * Cz + c0 + tx] = __float2half(smt[tx][ty + i * 8]);
}

// ---------------- fp16 tensor-core xp GEMM (layer 1 only) ----------------
#define BKP 40
#define ASZ (128 * BKP * 2)
__global__ void __launch_bounds__(256)
gemm_xp16(const __half* __restrict__ A,
          const __half* __restrict__ Bw,
          const float* __restrict__ bias,
          float* __restrict__ Cout)
{
    __shared__ __half sbuf[2 * 2 * 128 * BKP];
    const uint32_t s0 = smem_u32(sbuf);

    const int m0 = blockIdx.y * 128;
    const int g0 = blockIdx.x * 128;
    const int tid = threadIdx.x;
    const int w = tid >> 5;
    const int lane = tid & 31;
    const int wm = (w >> 1) * 32;
    const int wn = (w & 1) * 64;

    float c_[2][8][4];
#pragma unroll
    for (int mt = 0; mt < 2; mt++)
#pragma unroll
        for (int q = 0; q < 8; q++)
#pragma unroll
            for (int i = 0; i < 4; i++) c_[mt][q][i] = 0.f;

    const int zr0 = tid >> 2, zs0 = tid & 3;
    const int zr1 = (tid + 256) >> 2, zs1 = tid & 3;

    const uint32_t a_off = (uint32_t)(((wm + (lane & 15)) * BKP + (lane >> 4) * 8) * 2);
    const uint32_t b_off = (uint32_t)(((wn + ((lane >> 4) & 1) * 8 + (lane & 7)) * BKP
                                      + ((lane >> 3) & 1) * 8) * 2);

    {
        cpa16(s0 + (zr0 * BKP + zs0 * 8) * 2, A + (size_t)(m0 + zr0) * Cz + zs0 * 8);
        cpa16(s0 + (zr1 * BKP + zs1 * 8) * 2, A + (size_t)(m0 + zr1) * Cz + zs1 * 8);
        cpa16(s0 + 2 * ASZ + (zr0 * BKP + zs0 * 8) * 2, Bw + (size_t)(g0 + zr0) * Cz + zs0 * 8);
        cpa16(s0 + 2 * ASZ + (zr1 * BKP + zs1 * 8) * 2, Bw + (size_t)(g0 + zr1) * Cz + zs1 * 8);
        cpa_commit();
    }

    for (int c = 0; c < 16; c++) {
        const int buf = c & 1;
        if (c < 15) {
            const int nb = buf ^ 1;
            const int k0 = (c + 1) * 32;
            cpa16(s0 + nb * ASZ + (zr0 * BKP + zs0 * 8) * 2,
                  A + (size_t)(m0 + zr0) * Cz + k0 + zs0 * 8);
            cpa16(s0 + nb * ASZ + (zr1 * BKP + zs1 * 8) * 2,
                  A + (size_t)(m0 + zr1) * Cz + k0 + zs1 * 8);
            cpa16(s0 + (2 + nb) * ASZ + (zr0 * BKP + zs0 * 8) * 2,
                  Bw + (size_t)(g0 + zr0) * Cz + k0 + zs0 * 8);
            cpa16(s0 + (2 + nb) * ASZ + (zr1 * BKP + zs1 * 8) * 2,
                  Bw + (size_t)(g0 + zr1) * Cz + k0 + zs1 * 8);
            cpa_commit();
            cpa_wait1();
        } else {
            cpa_wait0();
        }
        __syncthreads();

        const uint32_t ab = s0 + buf * ASZ + a_off;
        const uint32_t bb = s0 + (2 + buf) * ASZ + b_off;
#pragma unroll
        for (int ks = 0; ks < 2; ks++) {
            uint32_t a[2][4];
#pragma unroll
            for (int mt = 0; mt < 2; mt++)
                ldsm4(a[mt][0], a[mt][1], a[mt][2], a[mt][3],
                      ab + (uint32_t)(mt * 16 * BKP * 2 + ks * 32));
#pragma unroll
            for (int j = 0; j < 4; j++) {
                uint32_t r0, r1, r2, r3;
                ldsm4(r0, r1, r2, r3, bb + (uint32_t)(j * 16 * BKP * 2 + ks * 32));
                mma16816(c_[0][2 * j],     a[0][0], a[0][1], a[0][2], a[0][3], r0, r1);
                mma16816(c_[1][2 * j],     a[1][0], a[1][1], a[1][2], a[1][3], r0, r1);
                mma16816(c_[0][2 * j + 1], a[0][0], a[0][1], a[0][2], a[0][3], r2, r3);
                mma16816(c_[1][2 * j + 1], a[1][0], a[1][1], a[1][2], a[1][3], r2, r3);
            }
        }
        __syncthreads();
    }

#pragma unroll
    for (int q = 0; q < 8; q++) {
        const int gc = g0 + wn + q * 8 + (lane & 3) * 2;
        const float bv0 = bias[gc];
        const float bv1 = bias[gc + 1];
#pragma unroll
        for (int mt = 0; mt < 2; mt++) {
            const int r0 = m0 + wm + mt * 16 + (lane >> 2);
            float2 v0 = make_float2(c_[mt][q][0] + bv0, c_[mt][q][1] + bv1);
            float2 v1 = make_float2(c_[mt][q][2] + bv0, c_[mt][q][3] + bv1);
            *(float2*)&Cout[(size_t)r0 * Gz + gc] = v0;
            *(float2*)&Cout[(size_t)(r0 + 8) * Gz + gc] = v1;
        }
    }
}

// ---------------- fused 2-layer persistent recurrent kernel ----------------
// R13 structure + split flags with EARLY release of flag1 after epilogue-1.
// Steady state: both flag polls hit the fast path (peers released >=1.5K cyc ago).
// SMEM: Whh2 img 66560 | h1 16640 | h2 16640 | gs1 5120 | gs2 5120 = 110080 B
#define W2_OFF 0
#define H1_OFF 66560
#define H2_OFF 83200
#define GS1_OFF 99840
#define GS2_OFF 104960
#define REC_SMEM 110080
__global__ void __launch_bounds__(256, 1)
lstm_rec2(const uint32_t* __restrict__ wr1,
          const uint32_t* __restrict__ wr2,
          const __half* __restrict__ w2img,
          const float* __restrict__ xp,
          float* __restrict__ hseq)
{
    extern __shared__ __align__(16) char sm[];
    const uint32_t sbase = smem_u32(sm);
    float* gs1 = (float*)(sm + GS1_OFF);
    float* gs2 = (float*)(sm + GS2_OFF);

    const int tid  = threadIdx.x;
    const int w    = tid >> 5;
    const int lane = tid & 31;
    const int n    = blockIdx.x & 31;
    const int grp  = blockIdx.x >> 5;

    // ---- W_hh1 + W_ih2 register fragments ----
    uint32_t wB1[64], wB2[64];
    {
        const uint4* p1 = (const uint4*)(wr1 + (((size_t)n * 8 + w) * 32 + lane) * 64);
        const uint4* p2 = (const uint4*)(wr2 + (((size_t)n * 8 + w) * 32 + lane) * 64);
#pragma unroll
        for (int q = 0; q < 16; q++) {
            uint4 v1 = p1[q];
            wB1[q * 4 + 0] = v1.x; wB1[q * 4 + 1] = v1.y;
            wB1[q * 4 + 2] = v1.z; wB1[q * 4 + 3] = v1.w;
            uint4 v2 = p2[q];
            wB2[q * 4 + 0] = v2.x; wB2[q * 4 + 1] = v2.y;
            wB2[q * 4 + 2] = v2.z; wB2[q * 4 + 3] = v2.w;
        }
    }

    // ---- W_hh2 image into SMEM (one-time) ----
    {
        const char* src = (const char*)w2img + (size_t)n * (64 * K2P * 2);
        for (int z = tid; z < 4160; z += 256)
            cpa16(sbase + W2_OFF + z * 16, src + (size_t)z * 16);
        cpa_commit();
    }

    // epilogue mapping
    const int em   = tid >> 4;
    const int col  = tid & 15;
    const int gcol = n * 16 + col;
    float c1reg = 0.f, c2reg = 0.f;
    const float b2i = g_bias2[0 * Hz + gcol];
    const float b2f = g_bias2[1 * Hz + gcol];
    const float b2g = g_bias2[2 * Hz + gcol];
    const float b2o = g_bias2[3 * Hz + gcol];

    g_h1[grp][0][em * Hz + gcol] = __float2half(0.f);
    g_h2[grp][0][em * Hz + gcol] = __float2half(0.f);
    g_h2[grp][1][em * Hz + gcol] = __float2half(0.f);

    const unsigned long long base1 = g_flag1[grp][n][0];
    const unsigned long long base2 = g_flag2[grp][n][0];
    __syncthreads();
    if (tid == 0) {
        flag_release(&g_flag1[grp][n][0], base1 + 1ULL);
        flag_release(&g_flag2[grp][n][0], base2 + 1ULL);
    }

    // ldmatrix addressing (conflict-free strides)
    const uint32_t a1_base = sbase + H1_OFF + (uint32_t)((lane & 15) * HROWB + (lane >> 4) * 16);
    const uint32_t a2_base = sbase + H2_OFF + (uint32_t)((lane & 15) * HROWB + (lane >> 4) * 16);
    const uint32_t b2_base = sbase + W2_OFF +
        (uint32_t)((8 * w + (lane & 7)) * (K2P * 2) + (lane >> 3) * 16);
    const int crow = lane >> 2;
    const int sc   = (w >> 1) * 16 + (w & 1) * 8 + (lane & 3) * 2;

    for (int r = 0; r <= Tz; r++) {
        // ---- xp prefetch BEFORE the barrier (DRAM latency hidden) ----
        const int tq = (r < Tz) ? r : (Tz - 1);
        const float* xb = xp + ((size_t)(grp * 16 + em) * Tz + tq) * Gz + gcol;
        float xq0 = __ldg(xb);
        float xq1 = __ldg(xb + 512);
        float xq2 = __ldg(xb + 1024);
        float xq3 = __ldg(xb + 1536);

        // ---- wait both flags (flag1: h1(r-1); flag2: h2 tile, >=1 round stale) ----
        if (tid < NSLICE) {
            while (flag_acquire(&g_flag1[grp][tid][0]) < base1 + 1ULL + (unsigned long long)r) { }
        } else if (tid < 2 * NSLICE) {
            while (flag_acquire(&g_flag2[grp][tid - NSLICE][0]) < base2 + 1ULL + (unsigned long long)r) { }
        }
        __syncthreads();

        // ---- cp.async h1(r-1) [group A], then h2 [group B] ----
        {
            const char* s1 = (const char*)&g_h1[grp][r & 1][0];
            const char* s2 = (const char*)&g_h2[grp][r & 1][0];
#pragma unroll
            for (int q = 0; q < 4; q++) {
                int z = q * 256 + tid;
                uint32_t off = (uint32_t)((z >> 6) * HROWB + (z & 63) * 16);
                cpa16(sbase + H1_OFF + off, s1 + z * 16);
            }
            cpa_commit();
#pragma unroll
            for (int q = 0; q < 4; q++) {
                int z = q * 256 + tid;
                uint32_t off = (uint32_t)((z >> 6) * HROWB + (z & 63) * 16);
                cpa16(sbase + H2_OFF + off, s2 + z * 16);
            }
            cpa_commit();
        }

        // ---- wait h1 only; part1 overlaps the h2 fetch ----
        cpa_wait1();
        __syncthreads();

        float c1_[4] = {0.f, 0.f, 0.f, 0.f};
        float c2_[4] = {0.f, 0.f, 0.f, 0.f};

        // part 1: A = h1(r-1); layer-1 (wB1) and layer-2-ih (wB2) from regs
#pragma unroll
        for (int ks = 0; ks < 32; ks++) {
            uint32_t a0, a1, a2, a3;
            ldsm4(a0, a1, a2, a3, a1_base + (uint32_t)(ks * 32));
            mma16816(c1_, a0, a1, a2, a3, wB1[2 * ks], wB1[2 * ks + 1]);
            mma16816(c2_, a0, a1, a2, a3, wB2[2 * ks], wB2[2 * ks + 1]);
        }

        // ---- stage gs1, epilogue1, publish h1(r), EARLY release flag1 ----
        gs1[crow * 80 + sc]           = c1_[0];
        gs1[crow * 80 + sc + 1]       = c1_[1];
        gs1[(crow + 8) * 80 + sc]     = c1_[2];
        gs1[(crow + 8) * 80 + sc + 1] = c1_[3];
        __syncthreads();

        if (r < Tz) {
            float gi = gs1[em * 80 + col]      + xq0;
            float gf = gs1[em * 80 + 16 + col] + xq1;
            float gg = gs1[em * 80 + 32 + col] + xq2;
            float go = gs1[em * 80 + 48 + col] + xq3;
            float iv = sig_(gi), fv = sig_(gf), gv = tanh_(gg), ov = sig_(go);
            c1reg = fv * c1reg + iv * gv;
            float h1v = ov * tanh_(c1reg);
            g_h1[grp][(r + 1) & 1][em * Hz + gcol] = __float2half(h1v);
        }
        __syncthreads();
        if (tid == 0) flag_release(&g_flag1[grp][n][0], base1 + 2ULL + (unsigned long long)r);

        // ---- shadow: wait h2, part2 ----
        cpa_wait0();
        __syncthreads();

#pragma unroll
        for (int ks2 = 0; ks2 < 16; ks2++) {
            uint32_t b0, b1, b2, b3;
            ldsm4(b0, b1, b2, b3, b2_base + (uint32_t)(ks2 * 64));
            uint32_t a0, a1, a2, a3;
            ldsm4(a0, a1, a2, a3, a2_base + (uint32_t)((2 * ks2) * 32));
            mma16816(c2_, a0, a1, a2, a3, b0, b1);
            ldsm4(a0, a1, a2, a3, a2_base + (uint32_t)((2 * ks2 + 1) * 32));
            mma16816(c2_, a0, a1, a2, a3, b2, b3);
        }

        // ---- stage gs2, epilogue2, publish h2(r-1), release flag2 ----
        gs2[crow * 80 + sc]           = c2_[0];
        gs2[crow * 80 + sc + 1]       = c2_[1];
        gs2[(crow + 8) * 80 + sc]     = c2_[2];
        gs2[(crow + 8) * 80 + sc + 1] = c2_[3];
        __syncthreads();

        float h2v = 0.f;
        const bool do2 = (r > 0);
        if (do2) {
            float gi = gs2[em * 80 + col]      + b2i;
            float gf = gs2[em * 80 + 16 + col] + b2f;
            float gg = gs2[em * 80 + 32 + col] + b2g;
            float go = gs2[em * 80 + 48 + col] + b2o;
            float iv = sig_(gi), fv = sig_(gf), gv = tanh_(gg), ov = sig_(go);
            c2reg = fv * c2reg + iv * gv;
            h2v = ov * tanh_(c2reg);
            g_h2[grp][(r + 1) & 1][em * Hz + gcol] = __float2half(h2v);
        }
        __syncthreads();
        if (tid == 0) flag_release(&g_flag2[grp][n][0], base2 + 2ULL + (unsigned long long)r);
        if (do2)
            hseq[((size_t)(grp * 16 + em) * Tz + (r - 1)) * Hz + gcol] = h2v;
    }
}

// ---------------- final transpose: hseq [b][t][c] -> out [b][c][t] ----------
__global__ void __launch_bounds__(256)
transpose_out(const float* __restrict__ hseq, float* __restrict__ out)
{
    __shared__ float smt[32][33];
    const int t0 = blockIdx.x * 32;
    const int c0 = blockIdx.y * 32;
    const int b  = blockIdx.z;
    const int tx = threadIdx.x;
    const int ty = threadIdx.y;

#pragma unroll
    for (int i = 0; i < 4; i++)
        smt[ty + i * 8][tx] = hseq[((size_t)b * Tz + t0 + ty + i * 8) * Hz + c0 + tx];
    __syncthreads();
#pragma unroll
    for (int i = 0; i < 4; i++)
        out[(size_t)b * (Hz * Tz) + (size_t)(c0 + ty + i * 8) * Tz + t0 + tx] = smt[tx][ty + i * 8];
}

// ---------------- host launcher ----------------
extern "C" void kernel_launch(void* const* d_in, const int* in_sizes, int n_in,
                              void* d_out, int out_size)
{
    const float* x     = (const float*)d_in[0];
    const float* W_ih1 = (const float*)d_in[1];
    const float* W_hh1 = (const float*)d_in[2];
    const float* b_ih1 = (const float*)d_in[3];
    const float* b_hh1 = (const float*)d_in[4];
    const float* W_ih2 = (const float*)d_in[5];
    const float* W_hh2 = (const float*)d_in[6];
    const float* b_ih2 = (const float*)d_in[7];
    const float* b_hh2 = (const float*)d_in[8];
    float* out = (float*)d_out;

    float *p_xp, *p_hseq, *p_b1;
    __half *p_xh, *p_w16a, *p_w2img;
    uint32_t *p_wr1, *p_wr2;
    cudaGetSymbolAddress((void**)&p_xp,    g_xp);
    cudaGetSymbolAddress((void**)&p_hseq,  g_hseq);
    cudaGetSymbolAddress((void**)&p_xh,    g_xh);
    cudaGetSymbolAddress((void**)&p_w16a,  g_w16a);
    cudaGetSymbolAddress((void**)&p_b1,    g_bias1);
    cudaGetSymbolAddress((void**)&p_wr1,   g_wr1);
    cudaGetSymbolAddress((void**)&p_wr2,   g_wr2);
    cudaGetSymbolAddress((void**)&p_w2img, g_w2img);

    cudaFuncSetAttribute(lstm_rec2, cudaFuncAttributeMaxDynamicSharedMemorySize, REC_SMEM);

    // prep
    lstm_prep<<<(Gz * Cz + 255) / 256, 256>>>(W_ih1, b_ih1, b_hh1, b_ih2, b_hh2);
    prep_wr<<<(2 * NSLICE * 8 * 32 * 32 + 255) / 256, 256>>>(W_hh1, W_ih2);
    prep_w2img<<<(NSLICE * 64 * 512 + 255) / 256, 256>>>(W_hh2);
    convert_x<<<dim3(Tz / 32, Cz / 32, Bz), dim3(32, 8)>>>(x, p_xh);

    // xp1 = x16 @ W_ih1^T + bias1
    gemm_xp16<<<dim3(Gz / 128, Mz / 128), 256>>>(p_xh, p_w16a, p_b1, p_xp);

    // fused 2-layer recurrence -> g_hseq [m][c]
    lstm_rec2<<<NGRP * NSLICE, 256, REC_SMEM>>>(p_wr1, p_wr2, p_w2img, p_xp, p_hseq);

    // final transpose -> out (B, H, T)
    transpose_out<<<dim3(Tz / 32, Hz / 32, Bz), dim3(32, 8)>>>(p_hseq, out);
}

// round 15
// speedup vs baseline: 1.5301x; 1.1986x over previous
#include <cuda_runtime.h>
#include <cuda_fp16.h>
#include <math.h>
#include <stdint.h>

// Problem constants
#define Bz 64
#define Tz 512
#define Cz 512
#define Hz 512
#define Gz 2048    // 4*H
#define Mz (Bz*Tz) // 32768
#define NSLICE 32  // h-col slices (CTAs per group)
#define NGRP 4     // batch groups (16 rows each)
#define K2P 520    // W_hh2 image row stride (halves) -> 1040 B, conflict-free
#define HROWB 1040 // h tile row stride (bytes), conflict-free

// ---------------- device scratch (static, no allocation) ----------------
__device__ float g_xp[(size_t)Mz * Gz];      // [m][g]
__device__ float g_hseq[(size_t)Mz * Hz];    // [m][c]
__device__ __half g_xh[(size_t)Mz * Cz];     // fp16 x [m][c]
__device__ __half g_w16a[Gz * Cz];           // W_ih1 fp16 [g][k]
__device__ float g_bias1[Gz];
__device__ float g_bias2[Gz];
// B fragments: [n][ws][j][lane][ks*2+r]; ws<4: Whh1 gate ws, ws>=4: Wih2 gate ws-4
__device__ uint32_t g_wr[(size_t)NSLICE * 8 * 2 * 32 * 64];   // 4 MB
__device__ __half g_w2img[(size_t)NSLICE * 64 * K2P];         // per-slice W_hh2 images
__device__ __half g_h1[NGRP][2][16 * Hz];    // h1 fp16 double buffer
__device__ __half g_h2[NGRP][2][16 * Hz];    // h2 fp16 double buffer
__device__ unsigned long long g_flag1[NGRP][NSLICE][16];  // h1-ready flags (128B pad)
__device__ unsigned long long g_flag2[NGRP][NSLICE][16];  // h2-ready flags (128B pad)

// ==================== helpers ====================
__device__ __forceinline__ uint32_t smem_u32(const void* p) {
    uint32_t a;
    asm("{ .reg .u64 t; cvta.to.shared.u64 t, %1; cvt.u32.u64 %0, t; }" : "=r"(a) : "l"(p));
    return a;
}
__device__ __forceinline__ void cpa16(uint32_t dst_smem, const void* src) {
    asm volatile("cp.async.cg.shared.global [%0], [%1], 16;" :: "r"(dst_smem), "l"(src));
}
__device__ __forceinline__ void cpa_commit() { asm volatile("cp.async.commit_group;"); }
__device__ __forceinline__ void cpa_wait0()  { asm volatile("cp.async.wait_group 0;" ::: "memory"); }
__device__ __forceinline__ void cpa_wait1()  { asm volatile("cp.async.wait_group 1;" ::: "memory"); }

__device__ __forceinline__ void flag_release(unsigned long long* p, unsigned long long v) {
    asm volatile("st.release.gpu.global.u64 [%0], %1;" :: "l"(p), "l"(v) : "memory");
}
__device__ __forceinline__ unsigned long long flag_acquire(const unsigned long long* p) {
    unsigned long long v;
    asm volatile("ld.acquire.gpu.global.u64 %0, [%1];" : "=l"(v) : "l"(p) : "memory");
    return v;
}

#define BAR_SYNC(id, cnt) asm volatile("bar.sync %0, %1;" :: "r"(id), "r"(cnt) : "memory")

__device__ __forceinline__ void mma16816(float* c,
    uint32_t a0, uint32_t a1, uint32_t a2, uint32_t a3, uint32_t b0, uint32_t b1)
{
    asm volatile(
        "mma.sync.aligned.m16n8k16.row.col.f32.f16.f16.f32 "
        "{%0,%1,%2,%3}, {%4,%5,%6,%7}, {%8,%9}, {%0,%1,%2,%3};"
        : "+f"(c[0]), "+f"(c[1]), "+f"(c[2]), "+f"(c[3])
        : "r"(a0), "r"(a1), "r"(a2), "r"(a3), "r"(b0), "r"(b1));
}

__device__ __forceinline__ void ldsm4(uint32_t& a0, uint32_t& a1, uint32_t& a2, uint32_t& a3,
                                      uint32_t addr)
{
    asm volatile("ldmatrix.sync.aligned.m8n8.x4.shared.b16 {%0,%1,%2,%3}, [%4];"
                 : "=r"(a0), "=r"(a1), "=r"(a2), "=r"(a3) : "r"(addr));
}

__device__ __forceinline__ float sig_(float x)  { return __fdividef(1.f, 1.f + __expf(-x)); }
__device__ __forceinline__ float tanh_(float x) { return 1.f - 2.f * __fdividef(1.f, __expf(2.f * x) + 1.f); }

// ---------------- prep: fp16 W_ih1, fold biases ----------------
__global__ void lstm_prep(const float* __restrict__ Wih1,
                          const float* __restrict__ bih1,
                          const float* __restrict__ bhh1,
                          const float* __restrict__ bih2,
                          const float* __restrict__ bhh2)
{
    int i = blockIdx.x * blockDim.x + threadIdx.x;
    if (i < Gz * Cz) g_w16a[i] = __float2half(Wih1[i]);
    if (i < Gz) {
        g_bias1[i] = bih1[i] + bhh1[i];
        g_bias2[i] = bih2[i] + bhh2[i];
    }
}

// ---------------- prep: Whh1/Wih2 -> per-warp-slot B fragments ----------------
// ws<4: W=Whh1, gate=ws; ws>=4: W=Wih2, gate=ws-4. ntile j: cols j*8..j*8+7.
__global__ void prep_wr(const float* __restrict__ Whh1, const float* __restrict__ Wih2)
{
    int e = blockIdx.x * blockDim.x + threadIdx.x;   // [n][ws][j][lane][ks]
    if (e >= NSLICE * 8 * 2 * 32 * 32) return;
    int ks   = e & 31;
    int lane = (e >> 5) & 31;
    int j    = (e >> 10) & 1;
    int ws   = (e >> 11) & 7;
    int n    = e >> 14;
    const float* W = (ws < 4) ? Whh1 : Wih2;
    int gate = ws & 3;
    int wrow = gate * Hz + n * 16 + j * 8 + (lane >> 2);
    int kb   = ks * 16 + (lane & 3) * 2;
    const float* r = W + (size_t)wrow * Hz;
    __half2 v0 = __floats2half2_rn(r[kb],     r[kb + 1]);
    __half2 v1 = __floats2half2_rn(r[kb + 8], r[kb + 9]);
    size_t idx = (((((size_t)n * 8 + ws) * 2 + j) * 32 + lane) * 32 + ks) * 2;
    g_wr[idx]     = *(const uint32_t*)&v0;
    g_wr[idx + 1] = *(const uint32_t*)&v1;
}

// ---------------- prep: W_hh2 per-slice fp16 image (stride K2P) -----------
__global__ void prep_w2img(const float* __restrict__ Whh2)
{
    int e = blockIdx.x * blockDim.x + threadIdx.x;   // [n][q][k]
    if (e >= NSLICE * 64 * 512) return;
    int k = e & 511;
    int q = (e >> 9) & 63;
    int n = e >> 15;
    int row = (q >> 4) * Hz + n * 16 + (q & 15);
    g_w2img[((size_t)n * 64 + q) * K2P + k] = __float2half(Whh2[(size_t)row * Hz + k]);
}

// ---------------- convert x (B,C,T) -> fp16 [b*T+t][c] ----------------
__global__ void __launch_bounds__(256)
convert_x(const float* __restrict__ x, __half* __restrict__ xh)
{
    __shared__ float smt[32][33];
    const int t0 = blockIdx.x * 32;
    const int c0 = blockIdx.y * 32;
    const int b  = blockIdx.z;
    const int tx = threadIdx.x;
    const int ty = threadIdx.y;
#pragma unroll
    for (int i = 0; i < 4; i++)
        smt[ty + i * 8][tx] = x[(size_t)b * (Cz * Tz) + (size_t)(c0 + ty + i * 8) * Tz + t0 + tx];
    __syncthreads();
#pragma unroll
    for (int i = 0; i < 4; i++)
        xh[((size_t)b * Tz + t0 + ty + i * 8) * Cz + c0 + tx] = __float2half(smt[tx][ty + i * 8]);
}

// ---------------- fp16 tensor-core xp GEMM (layer 1 only) ----------------
#define BKP 40
#define ASZ (128 * BKP * 2)
__global__ void __launch_bounds__(256)
gemm_xp16(const __half* __restrict__ A,
          const __half* __restrict__ Bw,
          const float* __restrict__ bias,
          float* __restrict__ Cout)
{
    __shared__ __half sbuf[2 * 2 * 128 * BKP];
    const uint32_t s0 = smem_u32(sbuf);

    const int m0 = blockIdx.y * 128;
    const int g0 = blockIdx.x * 128;
    const int tid = threadIdx.x;
    const int w = tid >> 5;
    const int lane = tid & 31;
    const int wm = (w >> 1) * 32;
    const int wn = (w & 1) * 64;

    float c_[2][8][4];
#pragma unroll
    for (int mt = 0; mt < 2; mt++)
#pragma unroll
        for (int q = 0; q < 8; q++)
#pragma unroll
            for (int i = 0; i < 4; i++) c_[mt][q][i] = 0.f;

    const int zr0 = tid >> 2, zs0 = tid & 3;
    const int zr1 = (tid + 256) >> 2, zs1 = tid & 3;

    const uint32_t a_off = (uint32_t)(((wm + (lane & 15)) * BKP + (lane >> 4) * 8) * 2);
    const uint32_t b_off = (uint32_t)(((wn + ((lane >> 4) & 1) * 8 + (lane & 7)) * BKP
                                      + ((lane >> 3) & 1) * 8) * 2);

    {
        cpa16(s0 + (zr0 * BKP + zs0 * 8) * 2, A + (size_t)(m0 + zr0) * Cz + zs0 * 8);
        cpa16(s0 + (zr1 * BKP + zs1 * 8) * 2, A + (size_t)(m0 + zr1) * Cz + zs1 * 8);
        cpa16(s0 + 2 * ASZ + (zr0 * BKP + zs0 * 8) * 2, Bw + (size_t)(g0 + zr0) * Cz + zs0 * 8);
        cpa16(s0 + 2 * ASZ + (zr1 * BKP + zs1 * 8) * 2, Bw + (size_t)(g0 + zr1) * Cz + zs1 * 8);
        cpa_commit();
    }

    for (int c = 0; c < 16; c++) {
        const int buf = c & 1;
        if (c < 15) {
            const int nb = buf ^ 1;
            const int k0 = (c + 1) * 32;
            cpa16(s0 + nb * ASZ + (zr0 * BKP + zs0 * 8) * 2,
                  A + (size_t)(m0 + zr0) * Cz + k0 + zs0 * 8);
            cpa16(s0 + nb * ASZ + (zr1 * BKP + zs1 * 8) * 2,
                  A + (size_t)(m0 + zr1) * Cz + k0 + zs1 * 8);
            cpa16(s0 + (2 + nb) * ASZ + (zr0 * BKP + zs0 * 8) * 2,
                  Bw + (size_t)(g0 + zr0) * Cz + k0 + zs0 * 8);
            cpa16(s0 + (2 + nb) * ASZ + (zr1 * BKP + zs1 * 8) * 2,
                  Bw + (size_t)(g0 + zr1) * Cz + k0 + zs1 * 8);
            cpa_commit();
            cpa_wait1();
        } else {
            cpa_wait0();
        }
        __syncthreads();

        const uint32_t ab = s0 + buf * ASZ + a_off;
        const uint32_t bb = s0 + (2 + buf) * ASZ + b_off;
#pragma unroll
        for (int ks = 0; ks < 2; ks++) {
            uint32_t a[2][4];
#pragma unroll
            for (int mt = 0; mt < 2; mt++)
                ldsm4(a[mt][0], a[mt][1], a[mt][2], a[mt][3],
                      ab + (uint32_t)(mt * 16 * BKP * 2 + ks * 32));
#pragma unroll
            for (int j = 0; j < 4; j++) {
                uint32_t r0, r1, r2, r3;
                ldsm4(r0, r1, r2, r3, bb + (uint32_t)(j * 16 * BKP * 2 + ks * 32));
                mma16816(c_[0][2 * j],     a[0][0], a[0][1], a[0][2], a[0][3], r0, r1);
                mma16816(c_[1][2 * j],     a[1][0], a[1][1], a[1][2], a[1][3], r0, r1);
                mma16816(c_[0][2 * j + 1], a[0][0], a[0][1], a[0][2], a[0][3], r2, r3);
                mma16816(c_[1][2 * j + 1], a[1][0], a[1][1], a[1][2], a[1][3], r2, r3);
            }
        }
        __syncthreads();
    }

#pragma unroll
    for (int q = 0; q < 8; q++) {
        const int gc = g0 + wn + q * 8 + (lane & 3) * 2;
        const float bv0 = bias[gc];
        const float bv1 = bias[gc + 1];
#pragma unroll
        for (int mt = 0; mt < 2; mt++) {
            const int r0 = m0 + wm + mt * 16 + (lane >> 2);
            float2 v0 = make_float2(c_[mt][q][0] + bv0, c_[mt][q][1] + bv1);
            float2 v1 = make_float2(c_[mt][q][2] + bv0, c_[mt][q][3] + bv1);
            *(float2*)&Cout[(size_t)r0 * Gz + gc] = v0;
            *(float2*)&Cout[(size_t)(r0 + 8) * Gz + gc] = v1;
        }
    }
}

// ---------------- warp-specialized fused 2-layer recurrent kernel ----------
// Warps 0-3: layer 1 (critical loop). Warps 4-7: layer 2 (shadow loop).
// One full bar.sync(3,256) per round hands the h1 SMEM tile (double-buffered)
// from L1 to L2 and provides lockstep (deadlock-free, see analysis).
// SMEM: Whh2 66560 | h1b0 16640 | h1b1 16640 | h2 16640 | gs1 5120 | gs2 5120
#define W2_OFF   0
#define H1B0_OFF 66560
#define H1B1_OFF 83200
#define H2T_OFF  99840
#define GS1_OFF  116480
#define GS2_OFF  121600
#define REC_SMEM 126720
__global__ void __launch_bounds__(256, 1)
lstm_rec2(const uint32_t* __restrict__ wr,
          const __half* __restrict__ w2img,
          const float* __restrict__ xp,
          float* __restrict__ hseq)
{
    extern __shared__ __align__(16) char sm[];
    const uint32_t sbase = smem_u32(sm);
    float* gs1 = (float*)(sm + GS1_OFF);
    float* gs2 = (float*)(sm + GS2_OFF);

    const int tid  = threadIdx.x;
    const int w    = tid >> 5;
    const int lane = tid & 31;
    const int n    = blockIdx.x & 31;
    const int grp  = blockIdx.x >> 5;
    const bool isL1 = (w < 4);
    const int gate = w & 3;

    // ---- per-warp B fragments: 2 ntiles x 32 ksteps x 2 regs = 128 ----
    uint32_t wB[128];
    {
        const uint4* p = (const uint4*)(wr + ((((size_t)n * 8 + w) * 2) * 32 + lane) * 64);
        const uint4* q2 = (const uint4*)(wr + ((((size_t)n * 8 + w) * 2 + 1) * 32 + lane) * 64);
#pragma unroll
        for (int q = 0; q < 16; q++) {
            uint4 v = p[q];
            wB[q * 4 + 0] = v.x; wB[q * 4 + 1] = v.y;
            wB[q * 4 + 2] = v.z; wB[q * 4 + 3] = v.w;
            uint4 u = q2[q];
            wB[64 + q * 4 + 0] = u.x; wB[64 + q * 4 + 1] = u.y;
            wB[64 + q * 4 + 2] = u.z; wB[64 + q * 4 + 3] = u.w;
        }
    }

    // ---- W_hh2 image into SMEM (loaded by L2 threads) ----
    if (!isL1) {
        const char* src = (const char*)w2img + (size_t)n * (64 * K2P * 2);
        for (int z = tid - 128; z < 4160; z += 128)
            cpa16(sbase + W2_OFF + z * 16, src + (size_t)z * 16);
        cpa_commit();
        cpa_wait0();
    }

    // zero h buffers
    {
        const int et = tid & 127;
        const int em0 = et >> 3;
        const int c0 = (et & 7) * 2;
        if (isL1) {
            *(uint32_t*)&g_h1[grp][0][em0 * Hz + n * 16 + c0] = 0u;
        } else {
            *(uint32_t*)&g_h2[grp][0][em0 * Hz + n * 16 + c0] = 0u;
            *(uint32_t*)&g_h2[grp][1][em0 * Hz + n * 16 + c0] = 0u;
        }
    }

    const unsigned long long base1 = g_flag1[grp][n][0];
    const unsigned long long base2 = g_flag2[grp][n][0];
    __syncthreads();
    if (tid == 0)   flag_release(&g_flag1[grp][n][0], base1 + 1ULL);
    if (tid == 128) flag_release(&g_flag2[grp][n][0], base2 + 1ULL);

    const int crow = lane >> 2;

    if (isL1) {
        // ================= LAYER 1 (critical path) =================
        const int em  = tid >> 3;          // 0..15
        const int c2l = (tid & 7) * 2;     // 0..14
        const int gc0 = n * 16 + c2l;
        float c1reg0 = 0.f, c1reg1 = 0.f;
        const uint32_t a1b[2] = {
            sbase + H1B0_OFF + (uint32_t)((lane & 15) * HROWB + (lane >> 4) * 16),
            sbase + H1B1_OFF + (uint32_t)((lane & 15) * HROWB + (lane >> 4) * 16)
        };
        const int sc0 = gate * 16 + (lane & 3) * 2;   // ntile j adds j*8

        for (int r = 0; r <= Tz; r++) {
            // xp prefetch (hidden under flag wait)
            const int tq = (r < Tz) ? r : (Tz - 1);
            const float* xb = xp + ((size_t)(grp * 16 + em) * Tz + tq) * Gz + gc0;
            float2 xq0 = *(const float2*)(xb);
            float2 xq1 = *(const float2*)(xb + 512);
            float2 xq2 = *(const float2*)(xb + 1024);
            float2 xq3 = *(const float2*)(xb + 1536);

            // wait peers' h1(r-1)
            if (tid < NSLICE) {
                while (flag_acquire(&g_flag1[grp][tid][0]) < base1 + 1ULL + (unsigned long long)r) { }
            }
            BAR_SYNC(1, 128);

            // fetch h1(r-1) into buf (r&1): 1024 segs / 128 thr = 8 each
            const uint32_t hoff = (r & 1) ? H1B1_OFF : H1B0_OFF;
            {
                const char* s1 = (const char*)&g_h1[grp][r & 1][0];
#pragma unroll
                for (int q = 0; q < 8; q++) {
                    int z = q * 128 + tid;
                    cpa16(sbase + hoff + (uint32_t)((z >> 6) * HROWB + (z & 63) * 16), s1 + z * 16);
                }
                cpa_commit();
                cpa_wait0();
            }
            BAR_SYNC(3, 256);   // tile ready: releases L2 too

            // MMA: 32 ldsm, 64 mma (2 ntiles share A)
            float c1_[2][4] = {{0.f,0.f,0.f,0.f},{0.f,0.f,0.f,0.f}};
            const uint32_t ab = a1b[r & 1];
#pragma unroll
            for (int ks = 0; ks < 32; ks++) {
                uint32_t a0, a1, a2, a3;
                ldsm4(a0, a1, a2, a3, ab + (uint32_t)(ks * 32));
                mma16816(c1_[0], a0, a1, a2, a3, wB[2 * ks],      wB[2 * ks + 1]);
                mma16816(c1_[1], a0, a1, a2, a3, wB[64 + 2 * ks], wB[64 + 2 * ks + 1]);
            }

            // stage gs1
#pragma unroll
            for (int j = 0; j < 2; j++) {
                const int sc = sc0 + j * 8;
                gs1[crow * 80 + sc]           = c1_[j][0];
                gs1[crow * 80 + sc + 1]       = c1_[j][1];
                gs1[(crow + 8) * 80 + sc]     = c1_[j][2];
                gs1[(crow + 8) * 80 + sc + 1] = c1_[j][3];
            }
            BAR_SYNC(1, 128);

            // epilogue: 2 cols per thread
            if (r < Tz) {
                float h0, h1v;
                {
                    float gi = gs1[em * 80 + c2l]      + xq0.x;
                    float gf = gs1[em * 80 + 16 + c2l] + xq1.x;
                    float gg = gs1[em * 80 + 32 + c2l] + xq2.x;
                    float go = gs1[em * 80 + 48 + c2l] + xq3.x;
                    float iv = sig_(gi), fv = sig_(gf), gv = tanh_(gg), ov = sig_(go);
                    c1reg0 = fv * c1reg0 + iv * gv;
                    h0 = ov * tanh_(c1reg0);
                }
                {
                    float gi = gs1[em * 80 + c2l + 1]      + xq0.y;
                    float gf = gs1[em * 80 + 16 + c2l + 1] + xq1.y;
                    float gg = gs1[em * 80 + 32 + c2l + 1] + xq2.y;
                    float go = gs1[em * 80 + 48 + c2l + 1] + xq3.y;
                    float iv = sig_(gi), fv = sig_(gf), gv = tanh_(gg), ov = sig_(go);
                    c1reg1 = fv * c1reg1 + iv * gv;
                    h1v = ov * tanh_(c1reg1);
                }
                __half2 hp = __floats2half2_rn(h0, h1v);
                *(uint32_t*)&g_h1[grp][(r + 1) & 1][em * Hz + gc0] = *(const uint32_t*)&hp;
            }
            BAR_SYNC(1, 128);
            if (tid == 0) flag_release(&g_flag1[grp][n][0], base1 + 2ULL + (unsigned long long)r);
        }
    } else {
        // ================= LAYER 2 (shadow path) =================
        const int tid2 = tid - 128;
        const int em  = tid2 >> 3;
        const int c2l = (tid2 & 7) * 2;
        const int gc0 = n * 16 + c2l;
        float c2reg0 = 0.f, c2reg1 = 0.f;
        const float2 b2i = *(const float2*)&g_bias2[0 * Hz + gc0];
        const float2 b2f = *(const float2*)&g_bias2[1 * Hz + gc0];
        const float2 b2g = *(const float2*)&g_bias2[2 * Hz + gc0];
        const float2 b2o = *(const float2*)&g_bias2[3 * Hz + gc0];

        const uint32_t a1b[2] = {
            sbase + H1B0_OFF + (uint32_t)((lane & 15) * HROWB + (lane >> 4) * 16),
            sbase + H1B1_OFF + (uint32_t)((lane & 15) * HROWB + (lane >> 4) * 16)
        };
        const uint32_t a2_base = sbase + H2T_OFF + (uint32_t)((lane & 15) * HROWB + (lane >> 4) * 16);
        const uint32_t b2j[2] = {
            sbase + W2_OFF + (uint32_t)((16 * gate + (lane & 7)) * (K2P * 2) + (lane >> 3) * 16),
            sbase + W2_OFF + (uint32_t)((16 * gate + 8 + (lane & 7)) * (K2P * 2) + (lane >> 3) * 16)
        };
        const int sc0 = gate * 16 + (lane & 3) * 2;

        for (int r = 0; r <= Tz; r++) {
            // wait peers' h2 (>=1 round stale -> fast path)
            if (tid2 < NSLICE) {
                while (flag_acquire(&g_flag2[grp][tid2][0]) < base2 + 1ULL + (unsigned long long)r) { }
            }
            BAR_SYNC(2, 128);

            // fetch h2(r-2) into h2 tile (overlaps ih MMA)
            {
                const char* s2 = (const char*)&g_h2[grp][r & 1][0];
#pragma unroll
                for (int q = 0; q < 8; q++) {
                    int z = q * 128 + tid2;
                    cpa16(sbase + H2T_OFF + (uint32_t)((z >> 6) * HROWB + (z & 63) * 16), s2 + z * 16);
                }
                cpa_commit();
            }

            BAR_SYNC(3, 256);   // h1(r-1) tile ready

            // ih MMA: A = h1 tile buf(r&1), B = wB regs
            float c2_[2][4] = {{0.f,0.f,0.f,0.f},{0.f,0.f,0.f,0.f}};
            const uint32_t ab = a1b[r & 1];
#pragma unroll
            for (int ks = 0; ks < 32; ks++) {
                uint32_t a0, a1, a2, a3;
                ldsm4(a0, a1, a2, a3, ab + (uint32_t)(ks * 32));
                mma16816(c2_[0], a0, a1, a2, a3, wB[2 * ks],      wB[2 * ks + 1]);
                mma16816(c2_[1], a0, a1, a2, a3, wB[64 + 2 * ks], wB[64 + 2 * ks + 1]);
            }

            cpa_wait0();
            BAR_SYNC(2, 128);

            // hh MMA: A = h2 tile, B = Whh2 smem
#pragma unroll
            for (int ks2 = 0; ks2 < 16; ks2++) {
                uint32_t a00, a01, a02, a03, a10, a11, a12, a13;
                ldsm4(a00, a01, a02, a03, a2_base + (uint32_t)((2 * ks2) * 32));
                ldsm4(a10, a11, a12, a13, a2_base + (uint32_t)((2 * ks2 + 1) * 32));
#pragma unroll
                for (int j = 0; j < 2; j++) {
                    uint32_t b0, b1, b2, b3;
                    ldsm4(b0, b1, b2, b3, b2j[j] + (uint32_t)(ks2 * 64));
                    mma16816(c2_[j], a00, a01, a02, a03, b0, b1);
                    mma16816(c2_[j], a10, a11, a12, a13, b2, b3);
                }
            }

            // stage gs2
#pragma unroll
            for (int j = 0; j < 2; j++) {
                const int sc = sc0 + j * 8;
                gs2[crow * 80 + sc]           = c2_[j][0];
                gs2[crow * 80 + sc + 1]       = c2_[j][1];
                gs2[(crow + 8) * 80 + sc]     = c2_[j][2];
                gs2[(crow + 8) * 80 + sc + 1] = c2_[j][3];
            }
            BAR_SYNC(2, 128);

            // epilogue: 2 cols per thread
            float h0 = 0.f, h1v = 0.f;
            const bool do2 = (r > 0);
            if (do2) {
                {
                    float gi = gs2[em * 80 + c2l]      + b2i.x;
                    float gf = gs2[em * 80 + 16 + c2l] + b2f.x;
                    float gg = gs2[em * 80 + 32 + c2l] + b2g.x;
                    float go = gs2[em * 80 + 48 + c2l] + b2o.x;
                    float iv = sig_(gi), fv = sig_(gf), gv = tanh_(gg), ov = sig_(go);
                    c2reg0 = fv * c2reg0 + iv * gv;
                    h0 = ov * tanh_(c2reg0);
                }
                {
                    float gi = gs2[em * 80 + c2l + 1]      + b2i.y;
                    float gf = gs2[em * 80 + 16 + c2l + 1] + b2f.y;
                    float gg = gs2[em * 80 + 32 + c2l + 1] + b2g.y;
                    float go = gs2[em * 80 + 48 + c2l + 1] + b2o.y;
                    float iv = sig_(gi), fv = sig_(gf), gv = tanh_(gg), ov = sig_(go);
                    c2reg1 = fv * c2reg1 + iv * gv;
                    h1v = ov * tanh_(c2reg1);
                }
                __half2 hp = __floats2half2_rn(h0, h1v);
                *(uint32_t*)&g_h2[grp][(r + 1) & 1][em * Hz + gc0] = *(const uint32_t*)&hp;
            }
            BAR_SYNC(2, 128);
            if (tid == 128) flag_release(&g_flag2[grp][n][0], base2 + 2ULL + (unsigned long long)r);
            if (do2)
                *(float2*)&hseq[((size_t)(grp * 16 + em) * Tz + (r - 1)) * Hz + gc0] =
                    make_float2(h0, h1v);
        }
    }
}

// ---------------- final transpose: hseq [b][t][c] -> out [b][c][t] ----------
__global__ void __launch_bounds__(256)
transpose_out(const float* __restrict__ hseq, float* __restrict__ out)
{
    __shared__ float smt[32][33];
    const int t0 = blockIdx.x * 32;
    const int c0 = blockIdx.y * 32;
    const int b  = blockIdx.z;
    const int tx = threadIdx.x;
    const int ty = threadIdx.y;

#pragma unroll
    for (int i = 0; i < 4; i++)
        smt[ty + i * 8][tx] = hseq[((size_t)b * Tz + t0 + ty + i * 8) * Hz + c0 + tx];
    __syncthreads();
#pragma unroll
    for (int i = 0; i < 4; i++)
        out[(size_t)b * (Hz * Tz) + (size_t)(c0 + ty + i * 8) * Tz + t0 + tx] = smt[tx][ty + i * 8];
}

// ---------------- host launcher ----------------
extern "C" void kernel_launch(void* const* d_in, const int* in_sizes, int n_in,
                              void* d_out, int out_size)
{
    const float* x     = (const float*)d_in[0];
    const float* W_ih1 = (const float*)d_in[1];
    const float* W_hh1 = (const float*)d_in[2];
    const float* b_ih1 = (const float*)d_in[3];
    const float* b_hh1 = (const float*)d_in[4];
    const float* W_ih2 = (const float*)d_in[5];
    const float* W_hh2 = (const float*)d_in[6];
    const float* b_ih2 = (const float*)d_in[7];
    const float* b_hh2 = (const float*)d_in[8];
    float* out = (float*)d_out;

    float *p_xp, *p_hseq, *p_b1;
    __half *p_xh, *p_w16a, *p_w2img;
    uint32_t *p_wr;
    cudaGetSymbolAddress((void**)&p_xp,    g_xp);
    cudaGetSymbolAddress((void**)&p_hseq,  g_hseq);
    cudaGetSymbolAddress((void**)&p_xh,    g_xh);
    cudaGetSymbolAddress((void**)&p_w16a,  g_w16a);
    cudaGetSymbolAddress((void**)&p_b1,    g_bias1);
    cudaGetSymbolAddress((void**)&p_wr,    g_wr);
    cudaGetSymbolAddress((void**)&p_w2img, g_w2img);

    cudaFuncSetAttribute(lstm_rec2, cudaFuncAttributeMaxDynamicSharedMemorySize, REC_SMEM);

    // prep
    lstm_prep<<<(Gz * Cz + 255) / 256, 256>>>(W_ih1, b_ih1, b_hh1, b_ih2, b_hh2);
    prep_wr<<<(NSLICE * 8 * 2 * 32 * 32 + 255) / 256, 256>>>(W_hh1, W_ih2);
    prep_w2img<<<(NSLICE * 64 * 512 + 255) / 256, 256>>>(W_hh2);
    convert_x<<<dim3(Tz / 32, Cz / 32, Bz), dim3(32, 8)>>>(x, p_xh);

    // xp1 = x16 @ W_ih1^T + bias1
    gemm_xp16<<<dim3(Gz / 128, Mz / 128), 256>>>(p_xh, p_w16a, p_b1, p_xp);

    // warp-specialized fused 2-layer recurrence -> g_hseq [m][c]
    lstm_rec2<<<NGRP * NSLICE, 256, REC_SMEM>>>(p_wr, p_w2img, p_xp, p_hseq);

    // final transpose -> out (B, H, T)
    transpose_out<<<dim3(Tz / 32, Hz / 32, Bz), dim3(32, 8)>>>(p_hseq, out);
}